// round 10
// baseline (speedup 1.0000x reference)
#include <cuda_runtime.h>
#include <cuda_bf16.h>
#include <cstdint>

#define BATCH 4
#define CDIM  768
#define TDIM  2048
#define NHEAD 12
#define HDIM  64
#define QKVROWS (3 * CDIM)

// ---------------------------------------------------------------------------
// Device scratch
// ---------------------------------------------------------------------------
__device__ float g_qkv[(size_t)BATCH * QKVROWS * TDIM];   // (B, 3C, T) tf32-rounded
__device__ float g_o  [(size_t)BATCH * CDIM    * TDIM];   // (B, C, T) tf32-rounded
__device__ float g_x  [(size_t)BATCH * CDIM    * TDIM];   // x, tf32-rounded
__device__ float g_wq [(size_t)QKVROWS * CDIM];           // Wqkv, tf32-rounded
__device__ float g_wo [(size_t)CDIM * CDIM];              // Wout, tf32-rounded

__device__ __forceinline__ uint32_t f2tf32(float x) {
    uint32_t r;
    asm("cvt.rna.tf32.f32 %0, %1;" : "=r"(r) : "f"(x));
    return r;
}

__device__ __forceinline__ float ex2_approx(float x) {
    float r;
    asm("ex2.approx.f32 %0, %1;" : "=f"(r) : "f"(x));
    return r;
}

__device__ __forceinline__ void mma_tf32(float* c, const uint32_t* a, const uint32_t* b) {
    asm volatile(
        "mma.sync.aligned.m16n8k8.row.col.f32.tf32.tf32.f32 "
        "{%0,%1,%2,%3}, {%4,%5,%6,%7}, {%8,%9}, {%0,%1,%2,%3};\n"
        : "+f"(c[0]), "+f"(c[1]), "+f"(c[2]), "+f"(c[3])
        : "r"(a[0]), "r"(a[1]), "r"(a[2]), "r"(a[3]), "r"(b[0]), "r"(b[1]));
}

__device__ __forceinline__ uint32_t smem_u32(const void* p) {
    return (uint32_t)__cvta_generic_to_shared(p);
}

__device__ __forceinline__ void cp_async16(uint32_t dst, const void* src) {
    asm volatile("cp.async.cg.shared.global [%0], [%1], 16;\n"
                 :: "r"(dst), "l"(src));
}
#define CP_COMMIT() asm volatile("cp.async.commit_group;\n")

// ---------------------------------------------------------------------------
// Pre-round: out[i] = tf32_rna(in[i]) as f32 bit pattern
// ---------------------------------------------------------------------------
__global__ __launch_bounds__(256)
void round_tf32_kernel(const float* __restrict__ in, float* __restrict__ out, int n)
{
    int i = (blockIdx.x * 256 + threadIdx.x) * 4;
    if (i < n) {
        float4 v = *reinterpret_cast<const float4*>(in + i);
        float4 o;
        o.x = __uint_as_float(f2tf32(v.x));
        o.y = __uint_as_float(f2tf32(v.y));
        o.z = __uint_as_float(f2tf32(v.z));
        o.w = __uint_as_float(f2tf32(v.w));
        *reinterpret_cast<float4*>(out + i) = o;
    }
}

// ---------------------------------------------------------------------------
// tf32 GEMM with cp.async double buffering (identical to R7 best).
// ---------------------------------------------------------------------------
#define GA_W (128 * 36)
#define GB_W (32 * 136)
#define GEMM_SMEM_BYTES ((2 * GA_W + 2 * GB_W) * 4)

template<bool ROUND_OUT>
__global__ __launch_bounds__(256, 2)
void gemm_tf32_cp(const float* __restrict__ A,
                  const float* __restrict__ Bmat,
                  const float* __restrict__ bias,
                  float* __restrict__ Cmat,
                  int M, int N, int K)
{
    extern __shared__ uint32_t gsm[];

    const float* Bp = Bmat + (size_t)blockIdx.z * (size_t)K * N;
    float*       Cp = Cmat + (size_t)blockIdx.z * (size_t)M * N;

    const int tid  = threadIdx.x;
    const int lane = tid & 31;
    const int warp = tid >> 5;
    const int g    = lane >> 2;
    const int tig  = lane & 3;
    const int wm   = warp >> 2;
    const int wn   = warp & 3;
    const int row0 = blockIdx.y * 128;
    const int col0 = blockIdx.x * 128;

    const int am  = tid >> 3;
    const int ak4 = (tid & 7) * 4;
    const int bk  = tid >> 5;
    const int bn4 = (tid & 31) * 4;

    const uint32_t sbase = smem_u32(gsm);

    float acc[4][4][4];
    #pragma unroll
    for (int i = 0; i < 4; i++)
        #pragma unroll
        for (int j = 0; j < 4; j++)
            #pragma unroll
            for (int r = 0; r < 4; r++) acc[i][j][r] = 0.0f;

    const int KT = K >> 5;

    auto issue = [&](int s) {
        const int k0 = s * 32;
        const uint32_t abase = sbase + (unsigned)((s & 1) * GA_W) * 4u;
        const uint32_t bbase = sbase + (unsigned)(2 * GA_W + (s & 1) * GB_W) * 4u;
        #pragma unroll
        for (int l = 0; l < 4; l++) {
            int m = am + 32 * l;
            cp_async16(abase + (unsigned)(m * 36 + ak4) * 4u,
                       A + (size_t)(row0 + m) * K + k0 + ak4);
        }
        #pragma unroll
        for (int l = 0; l < 4; l++) {
            int k = bk + 8 * l;
            cp_async16(bbase + (unsigned)(k * 136 + bn4) * 4u,
                       Bp + (size_t)(k0 + k) * N + col0 + bn4);
        }
        CP_COMMIT();
    };

    issue(0);
    if (KT > 1) issue(1);

    for (int kt = 0; kt < KT; kt++) {
        const int buf = kt & 1;
        if (kt + 1 < KT) asm volatile("cp.async.wait_group 1;\n");
        else             asm volatile("cp.async.wait_group 0;\n");
        __syncthreads();

        const uint32_t* Ab = gsm + buf * GA_W;
        const uint32_t* Bb = gsm + 2 * GA_W + buf * GB_W;

        #pragma unroll
        for (int kk = 0; kk < 32; kk += 8) {
            uint32_t af[4][4];
            uint32_t bf[4][2];
            #pragma unroll
            for (int mi = 0; mi < 4; mi++) {
                int m = wm * 64 + mi * 16 + g;
                af[mi][0] = Ab[m * 36 + kk + tig];
                af[mi][1] = Ab[(m + 8) * 36 + kk + tig];
                af[mi][2] = Ab[m * 36 + kk + tig + 4];
                af[mi][3] = Ab[(m + 8) * 36 + kk + tig + 4];
            }
            #pragma unroll
            for (int ni = 0; ni < 4; ni++) {
                int n = wn * 32 + ni * 8 + g;
                bf[ni][0] = Bb[(kk + tig) * 136 + n];
                bf[ni][1] = Bb[(kk + tig + 4) * 136 + n];
            }
            #pragma unroll
            for (int mi = 0; mi < 4; mi++)
                #pragma unroll
                for (int ni = 0; ni < 4; ni++)
                    mma_tf32(acc[mi][ni], af[mi], bf[ni]);
        }

        __syncthreads();
        if (kt + 2 < KT) issue(kt + 2);
    }

    #pragma unroll
    for (int mi = 0; mi < 4; mi++) {
        int r0 = row0 + wm * 64 + mi * 16 + g;
        float b0 = bias[r0];
        float b1 = bias[r0 + 8];
        #pragma unroll
        for (int ni = 0; ni < 4; ni++) {
            int cc = col0 + wn * 32 + ni * 8 + tig * 2;
            float o00 = acc[mi][ni][0] + b0, o01 = acc[mi][ni][1] + b0;
            float o10 = acc[mi][ni][2] + b1, o11 = acc[mi][ni][3] + b1;
            if (ROUND_OUT) {
                o00 = __uint_as_float(f2tf32(o00));
                o01 = __uint_as_float(f2tf32(o01));
                o10 = __uint_as_float(f2tf32(o10));
                o11 = __uint_as_float(f2tf32(o11));
            }
            *reinterpret_cast<float2*>(Cp + (size_t)r0 * N + cc)       = make_float2(o00, o01);
            *reinterpret_cast<float2*>(Cp + (size_t)(r0 + 8) * N + cc) = make_float2(o10, o11);
        }
    }
}

// ---------------------------------------------------------------------------
// Flash attention v9: R7 math, cross-chunk software pipelined.
// Iteration kt: [S-MMA(kt+1)] -> [softmax(kt) on prev scores] -> [PV(kt)].
// S(kt+1) MMAs are independent of softmax(kt)/PV(kt) -> tensor pipe stays fed
// while MUFU/shuffle phases execute. sacc double-buffered via two named
// register arrays (no dynamic indexing).
// grid (T/256, H, B), 256 threads, warp tile 32t x 64s / 32t x 64d.
// ---------------------------------------------------------------------------
#define KS_P 72
#define VS_P 68
#define FA_TBLK 256
#define KSTG (64 * KS_P)
#define VSTG (64 * VS_P)
#define FA_NCHUNK (TDIM / 64)
#define FA_SMEM_WORDS (3 * KSTG + 3 * VSTG + TDIM)
#define FA_SMEM_BYTES (FA_SMEM_WORDS * 4)
#define LOG2E 1.44269504088896340736f

__global__ __launch_bounds__(256, 1)
void flash_attn_v9(const int* __restrict__ mask)
{
    extern __shared__ uint32_t fsm[];
    uint32_t* Ks      = fsm;                       // 3 stages [d][s] pitch 72
    uint32_t* Vs      = Ks + 3 * KSTG;             // 3 stages [d][s] pitch 68
    float*    maskAll = (float*)(Vs + 3 * VSTG);   // 2048 biases (pre-scaled by log2e)

    const int b    = blockIdx.z;
    const int h    = blockIdx.y;
    const int tt   = blockIdx.x;
    const int tid  = threadIdx.x;
    const int lane = tid & 31;
    const int warp = tid >> 5;
    const int g    = lane >> 2;
    const int tig  = lane & 3;
    const int tw   = warp * 32;

    const size_t base = (size_t)b * QKVROWS * TDIM;
    const float* qptr = g_qkv + base + (size_t)(h * HDIM) * TDIM + tt * FA_TBLK + tw;
    const float* kptr = g_qkv + base + (size_t)(CDIM + h * HDIM) * TDIM;
    const float* vptr = g_qkv + base + (size_t)(2 * CDIM + h * HDIM) * TDIM;

    const uint32_t kbase0 = smem_u32(Ks);
    const uint32_t vbase0 = smem_u32(Vs);

    auto issue = [&](int ch) {
        const uint32_t kb = kbase0 + (unsigned)((ch % 3) * KSTG) * 4u;
        const uint32_t vb = vbase0 + (unsigned)((ch % 3) * VSTG) * 4u;
        const int s0 = ch * 64;
        #pragma unroll
        for (int l = 0; l < 4; l++) {
            int lin = tid + l * 256;
            int d   = lin >> 4;
            int s4  = (lin & 15) * 4;
            cp_async16(kb + (unsigned)(d * KS_P + s4) * 4u,
                       kptr + (size_t)d * TDIM + s0 + s4);
            cp_async16(vb + (unsigned)(d * VS_P + s4) * 4u,
                       vptr + (size_t)d * TDIM + s0 + s4);
        }
        CP_COMMIT();
    };

    issue(0); issue(1); issue(2);

    // Q fragments in registers, loaded once (qkv already tf32-rounded bits).
    uint32_t Qf[2][8][4];
    #pragma unroll
    for (int mi = 0; mi < 2; mi++)
        #pragma unroll
        for (int kk = 0; kk < 8; kk++) {
            const float* qp = qptr + (size_t)(kk * 8 + tig) * TDIM + mi * 16 + g;
            Qf[mi][kk][0] = __float_as_uint(qp[0]);
            Qf[mi][kk][1] = __float_as_uint(qp[8]);
            Qf[mi][kk][2] = __float_as_uint(qp[4 * TDIM]);
            Qf[mi][kk][3] = __float_as_uint(qp[4 * TDIM + 8]);
        }

    // Whole-row mask biases, pre-scaled by log2(e)
    for (int i = tid; i < TDIM; i += 256)
        maskAll[i] = (mask[(size_t)b * TDIM + i] == 0) ? (-10000.0f * LOG2E) : 0.0f;

    float accO[2][8][4];
    #pragma unroll
    for (int mi = 0; mi < 2; mi++)
        #pragma unroll
        for (int ni = 0; ni < 8; ni++)
            #pragma unroll
            for (int r = 0; r < 4; r++) accO[mi][ni][r] = 0.0f;

    float rowl[2][2] = {{0.0f, 0.0f}, {0.0f, 0.0f}};

    const float sc2 = 0.125f * LOG2E;   // exp(s/8) = exp2(s*sc2)

    // --- helper: S-MMA for chunk ch into dst ---
    auto smma = [&](int ch, float (&dst)[2][8][4]) {
        const uint32_t* Kb = Ks + (ch % 3) * KSTG;
        #pragma unroll
        for (int mi = 0; mi < 2; mi++)
            #pragma unroll
            for (int ni = 0; ni < 8; ni++)
                #pragma unroll
                for (int r = 0; r < 4; r++) dst[mi][ni][r] = 0.0f;
        #pragma unroll
        for (int kk = 0; kk < 8; kk++) {
            uint32_t bf[8][2];
            #pragma unroll
            for (int ni = 0; ni < 8; ni++) {
                bf[ni][0] = Kb[(kk * 8 + tig) * KS_P + ni * 8 + g];
                bf[ni][1] = Kb[(kk * 8 + tig + 4) * KS_P + ni * 8 + g];
            }
            #pragma unroll
            for (int mi = 0; mi < 2; mi++)
                #pragma unroll
                for (int ni = 0; ni < 8; ni++)
                    mma_tf32(dst[mi][ni], Qf[mi][kk], bf[ni]);
        }
    };

    // --- one pipelined step: consume cur (chunk kt), produce nxt (kt+1) ---
    auto step = [&](int kt, float (&cur)[2][8][4], float (&nxt)[2][8][4]) {
        // ensure stages through kt+1 landed (issued through min(kt+2, N-1))
        if (kt <= FA_NCHUNK - 3) asm volatile("cp.async.wait_group 1;\n");
        else                     asm volatile("cp.async.wait_group 0;\n");
        __syncthreads();

        // 1) S(kt+1): independent MMA chain, keeps tensor pipe busy
        if (kt + 1 < FA_NCHUNK) smma(kt + 1, nxt);

        // 2) softmax numerators on chunk kt (MUFU/FMA overlap with tensor)
        const float* mb = maskAll + kt * 64;
        float rs[2][2] = {{0.0f, 0.0f}, {0.0f, 0.0f}};
        #pragma unroll
        for (int mi = 0; mi < 2; mi++)
            #pragma unroll
            for (int ni = 0; ni < 8; ni++) {
                int sb = ni * 8 + tig * 2;
                float b0 = mb[sb], b1 = mb[sb + 1];
                float p0 = ex2_approx(fmaf(cur[mi][ni][0], sc2, b0));
                float p1 = ex2_approx(fmaf(cur[mi][ni][1], sc2, b1));
                float p2 = ex2_approx(fmaf(cur[mi][ni][2], sc2, b0));
                float p3 = ex2_approx(fmaf(cur[mi][ni][3], sc2, b1));
                rs[mi][0] += p0 + p1;
                rs[mi][1] += p2 + p3;
                cur[mi][ni][0] = p0;
                cur[mi][ni][1] = p1;
                cur[mi][ni][2] = p2;
                cur[mi][ni][3] = p3;
            }
        #pragma unroll
        for (int mi = 0; mi < 2; mi++)
            #pragma unroll
            for (int j = 0; j < 2; j++) {
                float r = rs[mi][j];
                r += __shfl_xor_sync(0xffffffffu, r, 1);
                r += __shfl_xor_sync(0xffffffffu, r, 2);
                rowl[mi][j] += r;
            }

        // 3) O += P V for chunk kt (P relayout via quad shuffles)
        const uint32_t* Vb = Vs + (kt % 3) * VSTG;
        const int src0 = (lane & ~3) | (tig >> 1);
        const int src1 = src0 + 2;
        const bool podd = (tig & 1);
        #pragma unroll
        for (int kb = 0; kb < 8; kb++) {
            uint32_t bf[8][2];
            #pragma unroll
            for (int ni = 0; ni < 8; ni++) {
                bf[ni][0] = Vb[(ni * 8 + g) * VS_P + kb * 8 + tig];
                bf[ni][1] = Vb[(ni * 8 + g) * VS_P + kb * 8 + tig + 4];
            }
            #pragma unroll
            for (int mi = 0; mi < 2; mi++) {
                float t00 = __shfl_sync(0xffffffffu, cur[mi][kb][0], src0);
                float t01 = __shfl_sync(0xffffffffu, cur[mi][kb][1], src0);
                float t02 = __shfl_sync(0xffffffffu, cur[mi][kb][2], src0);
                float t03 = __shfl_sync(0xffffffffu, cur[mi][kb][3], src0);
                float t10 = __shfl_sync(0xffffffffu, cur[mi][kb][0], src1);
                float t11 = __shfl_sync(0xffffffffu, cur[mi][kb][1], src1);
                float t12 = __shfl_sync(0xffffffffu, cur[mi][kb][2], src1);
                float t13 = __shfl_sync(0xffffffffu, cur[mi][kb][3], src1);
                uint32_t a[4];
                a[0] = __float_as_uint(podd ? t01 : t00);
                a[1] = __float_as_uint(podd ? t03 : t02);
                a[2] = __float_as_uint(podd ? t11 : t10);
                a[3] = __float_as_uint(podd ? t13 : t12);
                #pragma unroll
                for (int ni = 0; ni < 8; ni++)
                    mma_tf32(accO[mi][ni], a, bf[ni]);
            }
        }

        __syncthreads();                // stage kt%3 fully consumed by all
        if (kt + 3 < FA_NCHUNK) issue(kt + 3);
    };

    // Prologue: wait for chunk 0, compute S(0)
    float saccA[2][8][4], saccB[2][8][4];
    asm volatile("cp.async.wait_group 2;\n");
    __syncthreads();
    smma(0, saccA);

    // Main pipelined loop (FA_NCHUNK is even)
    for (int kt2 = 0; kt2 < FA_NCHUNK; kt2 += 2) {
        step(kt2,     saccA, saccB);
        step(kt2 + 1, saccB, saccA);
    }

    // ---- epilogue: normalize, round to tf32 bits (GEMM3 eats raw) ----
    float* optr = g_o + (size_t)b * CDIM * TDIM + (size_t)(h * HDIM) * TDIM
                + tt * FA_TBLK + tw;
    #pragma unroll
    for (int mi = 0; mi < 2; mi++) {
        float il0 = 1.0f / rowl[mi][0];
        float il1 = 1.0f / rowl[mi][1];
        #pragma unroll
        for (int ni = 0; ni < 8; ni++) {
            int d = ni * 8 + tig * 2;
            float* op = optr + (size_t)d * TDIM + mi * 16 + g;
            op[0]        = __uint_as_float(f2tf32(accO[mi][ni][0] * il0));
            op[TDIM]     = __uint_as_float(f2tf32(accO[mi][ni][1] * il0));
            op[8]        = __uint_as_float(f2tf32(accO[mi][ni][2] * il1));
            op[TDIM + 8] = __uint_as_float(f2tf32(accO[mi][ni][3] * il1));
        }
    }
}

// ---------------------------------------------------------------------------
// kernel_launch (single stream, graph-safe)
// ---------------------------------------------------------------------------
extern "C" void kernel_launch(void* const* d_in, const int* in_sizes, int n_in,
                              void* d_out, int out_size)
{
    const float* x    = (const float*)d_in[0];
    const int*   mask = (const int*)  d_in[1];
    const float* Wqkv = (const float*)d_in[2];
    const float* bqkv = (const float*)d_in[3];
    const float* Wout = (const float*)d_in[4];
    const float* bout = (const float*)d_in[5];
    float*       out  = (float*)d_out;

    float *qkv_p, *o_p, *x_p, *wq_p, *wo_p;
    cudaGetSymbolAddress((void**)&qkv_p, g_qkv);
    cudaGetSymbolAddress((void**)&o_p,   g_o);
    cudaGetSymbolAddress((void**)&x_p,   g_x);
    cudaGetSymbolAddress((void**)&wq_p,  g_wq);
    cudaGetSymbolAddress((void**)&wo_p,  g_wo);

    cudaFuncSetAttribute(gemm_tf32_cp<true>,
                         cudaFuncAttributeMaxDynamicSharedMemorySize, GEMM_SMEM_BYTES);
    cudaFuncSetAttribute(gemm_tf32_cp<false>,
                         cudaFuncAttributeMaxDynamicSharedMemorySize, GEMM_SMEM_BYTES);
    cudaFuncSetAttribute(flash_attn_v9,
                         cudaFuncAttributeMaxDynamicSharedMemorySize, FA_SMEM_BYTES);

    // 0) pre-round inputs to tf32 bit patterns
    {
        const int nx = BATCH * CDIM * TDIM;
        const int nq = QKVROWS * CDIM;
        const int nw = CDIM * CDIM;
        round_tf32_kernel<<<nx / 1024, 256>>>(x,    x_p,  nx);
        round_tf32_kernel<<<nq / 1024, 256>>>(Wqkv, wq_p, nq);
        round_tf32_kernel<<<nw / 1024, 256>>>(Wout, wo_p, nw);
    }

    // 1) qkv = Wqkv @ x + bqkv  (output rounded to tf32 bits for flash)
    {
        dim3 grid(TDIM / 128, QKVROWS / 128, BATCH);
        gemm_tf32_cp<true><<<grid, 256, GEMM_SMEM_BYTES>>>(wq_p, x_p, bqkv, qkv_p,
                                                           QKVROWS, TDIM, CDIM);
    }
    // 2) fused flash attention (software pipelined)
    {
        dim3 grid(TDIM / FA_TBLK, NHEAD, BATCH);
        flash_attn_v9<<<grid, 256, FA_SMEM_BYTES>>>(mask);
    }
    // 3) out = Wout @ o + bout  (full f32 output)
    {
        dim3 grid(TDIM / 128, CDIM / 128, BATCH);
        gemm_tf32_cp<false><<<grid, 256, GEMM_SMEM_BYTES>>>(wo_p, o_p, bout, out,
                                                            CDIM, TDIM, CDIM);
    }
}

// round 11
// speedup vs baseline: 1.2176x; 1.2176x over previous
#include <cuda_runtime.h>
#include <cuda_bf16.h>
#include <cstdint>

#define BATCH 4
#define CDIM  768
#define TDIM  2048
#define NHEAD 12
#define HDIM  64
#define QKVROWS (3 * CDIM)

// ---------------------------------------------------------------------------
// Device scratch
// ---------------------------------------------------------------------------
__device__ float g_qkv[(size_t)BATCH * QKVROWS * TDIM];   // (B, 3C, T) tf32-rounded
__device__ float g_o  [(size_t)BATCH * CDIM    * TDIM];   // (B, C, T) tf32-rounded
__device__ float g_x  [(size_t)BATCH * CDIM    * TDIM];   // x, tf32-rounded
__device__ float g_wq [(size_t)QKVROWS * CDIM];           // Wqkv, tf32-rounded
__device__ float g_wo [(size_t)CDIM * CDIM];              // Wout, tf32-rounded

__device__ __forceinline__ uint32_t f2tf32(float x) {
    uint32_t r;
    asm("cvt.rna.tf32.f32 %0, %1;" : "=r"(r) : "f"(x));
    return r;
}

__device__ __forceinline__ float ex2_approx(float x) {
    float r;
    asm("ex2.approx.f32 %0, %1;" : "=f"(r) : "f"(x));
    return r;
}

__device__ __forceinline__ void mma_tf32(float* c, const uint32_t* a, const uint32_t* b) {
    asm volatile(
        "mma.sync.aligned.m16n8k8.row.col.f32.tf32.tf32.f32 "
        "{%0,%1,%2,%3}, {%4,%5,%6,%7}, {%8,%9}, {%0,%1,%2,%3};\n"
        : "+f"(c[0]), "+f"(c[1]), "+f"(c[2]), "+f"(c[3])
        : "r"(a[0]), "r"(a[1]), "r"(a[2]), "r"(a[3]), "r"(b[0]), "r"(b[1]));
}

__device__ __forceinline__ uint32_t smem_u32(const void* p) {
    return (uint32_t)__cvta_generic_to_shared(p);
}

__device__ __forceinline__ void cp_async16(uint32_t dst, const void* src) {
    asm volatile("cp.async.cg.shared.global [%0], [%1], 16;\n"
                 :: "r"(dst), "l"(src));
}
#define CP_COMMIT() asm volatile("cp.async.commit_group;\n")

// ---------------------------------------------------------------------------
// Pre-round: out[i] = tf32_rna(in[i]) as f32 bit pattern
// ---------------------------------------------------------------------------
__global__ __launch_bounds__(256)
void round_tf32_kernel(const float* __restrict__ in, float* __restrict__ out, int n)
{
    int i = (blockIdx.x * 256 + threadIdx.x) * 4;
    if (i < n) {
        float4 v = *reinterpret_cast<const float4*>(in + i);
        float4 o;
        o.x = __uint_as_float(f2tf32(v.x));
        o.y = __uint_as_float(f2tf32(v.y));
        o.z = __uint_as_float(f2tf32(v.z));
        o.w = __uint_as_float(f2tf32(v.w));
        *reinterpret_cast<float4*>(out + i) = o;
    }
}

// ---------------------------------------------------------------------------
// tf32 GEMM v2: 128x128 block tile, 128 threads (4 warps, 2x2), warp tile
// 64x64 -> 1.0 LDS per MMA (was 1.5). cp.async double buffering, 2 CTAs/SM.
// ---------------------------------------------------------------------------
#define GA_W (128 * 36)
#define GB_W (32 * 136)
#define GEMM_SMEM_BYTES ((2 * GA_W + 2 * GB_W) * 4)

template<bool ROUND_OUT>
__global__ __launch_bounds__(128, 2)
void gemm_tf32_cp(const float* __restrict__ A,
                  const float* __restrict__ Bmat,
                  const float* __restrict__ bias,
                  float* __restrict__ Cmat,
                  int M, int N, int K)
{
    extern __shared__ uint32_t gsm[];

    const float* Bp = Bmat + (size_t)blockIdx.z * (size_t)K * N;
    float*       Cp = Cmat + (size_t)blockIdx.z * (size_t)M * N;

    const int tid  = threadIdx.x;
    const int lane = tid & 31;
    const int warp = tid >> 5;
    const int g    = lane >> 2;
    const int tig  = lane & 3;
    const int wm   = warp >> 1;         // 0..1
    const int wn   = warp & 1;          // 0..1
    const int row0 = blockIdx.y * 128;
    const int col0 = blockIdx.x * 128;

    const uint32_t sbase = smem_u32(gsm);

    float acc[4][8][4];
    #pragma unroll
    for (int i = 0; i < 4; i++)
        #pragma unroll
        for (int j = 0; j < 8; j++)
            #pragma unroll
            for (int r = 0; r < 4; r++) acc[i][j][r] = 0.0f;

    const int KT = K >> 5;

    auto issue = [&](int s) {
        const int k0 = s * 32;
        const uint32_t abase = sbase + (unsigned)((s & 1) * GA_W) * 4u;
        const uint32_t bbase = sbase + (unsigned)(2 * GA_W + (s & 1) * GB_W) * 4u;
        #pragma unroll
        for (int l = 0; l < 8; l++) {           // A: 128x32, 1024 float4
            int lin = tid + l * 128;
            int m   = lin >> 3;
            int k4  = (lin & 7) * 4;
            cp_async16(abase + (unsigned)(m * 36 + k4) * 4u,
                       A + (size_t)(row0 + m) * K + k0 + k4);
        }
        #pragma unroll
        for (int l = 0; l < 8; l++) {           // B: 32x128, 1024 float4
            int lin = tid + l * 128;
            int k   = lin >> 5;
            int n4  = (lin & 31) * 4;
            cp_async16(bbase + (unsigned)(k * 136 + n4) * 4u,
                       Bp + (size_t)(k0 + k) * N + col0 + n4);
        }
        CP_COMMIT();
    };

    issue(0);
    if (KT > 1) issue(1);

    for (int kt = 0; kt < KT; kt++) {
        const int buf = kt & 1;
        if (kt + 1 < KT) asm volatile("cp.async.wait_group 1;\n");
        else             asm volatile("cp.async.wait_group 0;\n");
        __syncthreads();

        const uint32_t* Ab = gsm + buf * GA_W;
        const uint32_t* Bb = gsm + 2 * GA_W + buf * GB_W;

        #pragma unroll
        for (int kk = 0; kk < 32; kk += 8) {
            uint32_t af[4][4];
            uint32_t bf[8][2];
            #pragma unroll
            for (int mi = 0; mi < 4; mi++) {
                int m = wm * 64 + mi * 16 + g;
                af[mi][0] = Ab[m * 36 + kk + tig];
                af[mi][1] = Ab[(m + 8) * 36 + kk + tig];
                af[mi][2] = Ab[m * 36 + kk + tig + 4];
                af[mi][3] = Ab[(m + 8) * 36 + kk + tig + 4];
            }
            #pragma unroll
            for (int ni = 0; ni < 8; ni++) {
                int n = wn * 64 + ni * 8 + g;
                bf[ni][0] = Bb[(kk + tig) * 136 + n];
                bf[ni][1] = Bb[(kk + tig + 4) * 136 + n];
            }
            #pragma unroll
            for (int mi = 0; mi < 4; mi++)
                #pragma unroll
                for (int ni = 0; ni < 8; ni++)
                    mma_tf32(acc[mi][ni], af[mi], bf[ni]);
        }

        __syncthreads();
        if (kt + 2 < KT) issue(kt + 2);
    }

    #pragma unroll
    for (int mi = 0; mi < 4; mi++) {
        int r0 = row0 + wm * 64 + mi * 16 + g;
        float b0 = bias[r0];
        float b1 = bias[r0 + 8];
        #pragma unroll
        for (int ni = 0; ni < 8; ni++) {
            int cc = col0 + wn * 64 + ni * 8 + tig * 2;
            float o00 = acc[mi][ni][0] + b0, o01 = acc[mi][ni][1] + b0;
            float o10 = acc[mi][ni][2] + b1, o11 = acc[mi][ni][3] + b1;
            if (ROUND_OUT) {
                o00 = __uint_as_float(f2tf32(o00));
                o01 = __uint_as_float(f2tf32(o01));
                o10 = __uint_as_float(f2tf32(o10));
                o11 = __uint_as_float(f2tf32(o11));
            }
            *reinterpret_cast<float2*>(Cp + (size_t)r0 * N + cc)       = make_float2(o00, o01);
            *reinterpret_cast<float2*>(Cp + (size_t)(r0 + 8) * N + cc) = make_float2(o10, o11);
        }
    }
}

// ---------------------------------------------------------------------------
// Flash attention v7 (exact R7 best: 256 thr / 8 warps, 32t x 64s warp tile,
// Q frags in registers, no P cvt, 3-stage cp.async ring, ex2 softmax).
// ---------------------------------------------------------------------------
#define KS_P 72
#define VS_P 68
#define FA_TBLK 256
#define KSTG (64 * KS_P)
#define VSTG (64 * VS_P)
#define FA_NCHUNK (TDIM / 64)
#define FA_SMEM_WORDS (3 * KSTG + 3 * VSTG + TDIM)
#define FA_SMEM_BYTES (FA_SMEM_WORDS * 4)
#define LOG2E 1.44269504088896340736f

__global__ __launch_bounds__(256, 1)
void flash_attn_v7(const int* __restrict__ mask)
{
    extern __shared__ uint32_t fsm[];
    uint32_t* Ks      = fsm;                       // 3 stages [d][s] pitch 72
    uint32_t* Vs      = Ks + 3 * KSTG;             // 3 stages [d][s] pitch 68
    float*    maskAll = (float*)(Vs + 3 * VSTG);   // 2048 biases (pre-scaled by log2e)

    const int b    = blockIdx.z;
    const int h    = blockIdx.y;
    const int tt   = blockIdx.x;
    const int tid  = threadIdx.x;
    const int lane = tid & 31;
    const int warp = tid >> 5;
    const int g    = lane >> 2;
    const int tig  = lane & 3;
    const int tw   = warp * 32;

    const size_t base = (size_t)b * QKVROWS * TDIM;
    const float* qptr = g_qkv + base + (size_t)(h * HDIM) * TDIM + tt * FA_TBLK + tw;
    const float* kptr = g_qkv + base + (size_t)(CDIM + h * HDIM) * TDIM;
    const float* vptr = g_qkv + base + (size_t)(2 * CDIM + h * HDIM) * TDIM;

    const uint32_t kbase0 = smem_u32(Ks);
    const uint32_t vbase0 = smem_u32(Vs);

    auto issue = [&](int ch) {
        const uint32_t kb = kbase0 + (unsigned)((ch % 3) * KSTG) * 4u;
        const uint32_t vb = vbase0 + (unsigned)((ch % 3) * VSTG) * 4u;
        const int s0 = ch * 64;
        #pragma unroll
        for (int l = 0; l < 4; l++) {
            int lin = tid + l * 256;
            int d   = lin >> 4;
            int s4  = (lin & 15) * 4;
            cp_async16(kb + (unsigned)(d * KS_P + s4) * 4u,
                       kptr + (size_t)d * TDIM + s0 + s4);
            cp_async16(vb + (unsigned)(d * VS_P + s4) * 4u,
                       vptr + (size_t)d * TDIM + s0 + s4);
        }
        CP_COMMIT();
    };

    issue(0); issue(1); issue(2);

    // Q fragments in registers, loaded once (qkv already tf32-rounded bits).
    uint32_t Qf[2][8][4];
    #pragma unroll
    for (int mi = 0; mi < 2; mi++)
        #pragma unroll
        for (int kk = 0; kk < 8; kk++) {
            const float* qp = qptr + (size_t)(kk * 8 + tig) * TDIM + mi * 16 + g;
            Qf[mi][kk][0] = __float_as_uint(qp[0]);
            Qf[mi][kk][1] = __float_as_uint(qp[8]);
            Qf[mi][kk][2] = __float_as_uint(qp[4 * TDIM]);
            Qf[mi][kk][3] = __float_as_uint(qp[4 * TDIM + 8]);
        }

    // Whole-row mask biases, pre-scaled by log2(e)
    for (int i = tid; i < TDIM; i += 256)
        maskAll[i] = (mask[(size_t)b * TDIM + i] == 0) ? (-10000.0f * LOG2E) : 0.0f;

    float accO[2][8][4];
    #pragma unroll
    for (int mi = 0; mi < 2; mi++)
        #pragma unroll
        for (int ni = 0; ni < 8; ni++)
            #pragma unroll
            for (int r = 0; r < 4; r++) accO[mi][ni][r] = 0.0f;

    float rowl[2][2] = {{0.0f, 0.0f}, {0.0f, 0.0f}};

    const float sc2 = 0.125f * LOG2E;   // exp(s/8) = exp2(s*sc2)

    for (int kt = 0; kt < FA_NCHUNK; kt++) {
        if      (kt + 2 < FA_NCHUNK) asm volatile("cp.async.wait_group 2;\n");
        else if (kt + 1 < FA_NCHUNK) asm volatile("cp.async.wait_group 1;\n");
        else                         asm volatile("cp.async.wait_group 0;\n");
        __syncthreads();

        const uint32_t* Kb = Ks + (kt % 3) * KSTG;
        const uint32_t* Vb = Vs + (kt % 3) * VSTG;
        const float*    mb = maskAll + kt * 64;

        // ---- S = Q K^T, warp tile 32t x 64s ----
        float sacc[2][8][4];
        #pragma unroll
        for (int mi = 0; mi < 2; mi++)
            #pragma unroll
            for (int ni = 0; ni < 8; ni++)
                #pragma unroll
                for (int r = 0; r < 4; r++) sacc[mi][ni][r] = 0.0f;

        #pragma unroll
        for (int kk = 0; kk < 8; kk++) {
            uint32_t bf[8][2];
            #pragma unroll
            for (int ni = 0; ni < 8; ni++) {
                bf[ni][0] = Kb[(kk * 8 + tig) * KS_P + ni * 8 + g];
                bf[ni][1] = Kb[(kk * 8 + tig + 4) * KS_P + ni * 8 + g];
            }
            #pragma unroll
            for (int mi = 0; mi < 2; mi++)
                #pragma unroll
                for (int ni = 0; ni < 8; ni++)
                    mma_tf32(sacc[mi][ni], Qf[mi][kk], bf[ni]);
        }

        // ---- softmax numerators: p = ex2(s*sc2 + bias); P stays raw f32 ----
        float rs[2][2] = {{0.0f, 0.0f}, {0.0f, 0.0f}};
        #pragma unroll
        for (int mi = 0; mi < 2; mi++)
            #pragma unroll
            for (int ni = 0; ni < 8; ni++) {
                int sb = ni * 8 + tig * 2;
                float b0 = mb[sb], b1 = mb[sb + 1];
                float p0 = ex2_approx(fmaf(sacc[mi][ni][0], sc2, b0));
                float p1 = ex2_approx(fmaf(sacc[mi][ni][1], sc2, b1));
                float p2 = ex2_approx(fmaf(sacc[mi][ni][2], sc2, b0));
                float p3 = ex2_approx(fmaf(sacc[mi][ni][3], sc2, b1));
                rs[mi][0] += p0 + p1;
                rs[mi][1] += p2 + p3;
                sacc[mi][ni][0] = p0;
                sacc[mi][ni][1] = p1;
                sacc[mi][ni][2] = p2;
                sacc[mi][ni][3] = p3;
            }
        #pragma unroll
        for (int mi = 0; mi < 2; mi++)
            #pragma unroll
            for (int j = 0; j < 2; j++) {
                float r = rs[mi][j];
                r += __shfl_xor_sync(0xffffffffu, r, 1);
                r += __shfl_xor_sync(0xffffffffu, r, 2);
                rowl[mi][j] += r;
            }

        // ---- O += P V, P fragments via quad shuffles ----
        const int src0 = (lane & ~3) | (tig >> 1);
        const int src1 = src0 + 2;
        const bool podd = (tig & 1);
        #pragma unroll
        for (int kb = 0; kb < 8; kb++) {
            uint32_t bf[8][2];
            #pragma unroll
            for (int ni = 0; ni < 8; ni++) {
                bf[ni][0] = Vb[(ni * 8 + g) * VS_P + kb * 8 + tig];
                bf[ni][1] = Vb[(ni * 8 + g) * VS_P + kb * 8 + tig + 4];
            }
            #pragma unroll
            for (int mi = 0; mi < 2; mi++) {
                float t00 = __shfl_sync(0xffffffffu, sacc[mi][kb][0], src0);
                float t01 = __shfl_sync(0xffffffffu, sacc[mi][kb][1], src0);
                float t02 = __shfl_sync(0xffffffffu, sacc[mi][kb][2], src0);
                float t03 = __shfl_sync(0xffffffffu, sacc[mi][kb][3], src0);
                float t10 = __shfl_sync(0xffffffffu, sacc[mi][kb][0], src1);
                float t11 = __shfl_sync(0xffffffffu, sacc[mi][kb][1], src1);
                float t12 = __shfl_sync(0xffffffffu, sacc[mi][kb][2], src1);
                float t13 = __shfl_sync(0xffffffffu, sacc[mi][kb][3], src1);
                uint32_t a[4];
                a[0] = __float_as_uint(podd ? t01 : t00);
                a[1] = __float_as_uint(podd ? t03 : t02);
                a[2] = __float_as_uint(podd ? t11 : t10);
                a[3] = __float_as_uint(podd ? t13 : t12);
                #pragma unroll
                for (int ni = 0; ni < 8; ni++)
                    mma_tf32(accO[mi][ni], a, bf[ni]);
            }
        }

        __syncthreads();
        if (kt + 3 < FA_NCHUNK) issue(kt + 3);
    }

    // ---- epilogue: normalize, round to tf32 bits (GEMM3 eats raw) ----
    float* optr = g_o + (size_t)b * CDIM * TDIM + (size_t)(h * HDIM) * TDIM
                + tt * FA_TBLK + tw;
    #pragma unroll
    for (int mi = 0; mi < 2; mi++) {
        float il0 = 1.0f / rowl[mi][0];
        float il1 = 1.0f / rowl[mi][1];
        #pragma unroll
        for (int ni = 0; ni < 8; ni++) {
            int d = ni * 8 + tig * 2;
            float* op = optr + (size_t)d * TDIM + mi * 16 + g;
            op[0]        = __uint_as_float(f2tf32(accO[mi][ni][0] * il0));
            op[TDIM]     = __uint_as_float(f2tf32(accO[mi][ni][1] * il0));
            op[8]        = __uint_as_float(f2tf32(accO[mi][ni][2] * il1));
            op[TDIM + 8] = __uint_as_float(f2tf32(accO[mi][ni][3] * il1));
        }
    }
}

// ---------------------------------------------------------------------------
// kernel_launch (single stream, graph-safe)
// ---------------------------------------------------------------------------
extern "C" void kernel_launch(void* const* d_in, const int* in_sizes, int n_in,
                              void* d_out, int out_size)
{
    const float* x    = (const float*)d_in[0];
    const int*   mask = (const int*)  d_in[1];
    const float* Wqkv = (const float*)d_in[2];
    const float* bqkv = (const float*)d_in[3];
    const float* Wout = (const float*)d_in[4];
    const float* bout = (const float*)d_in[5];
    float*       out  = (float*)d_out;

    float *qkv_p, *o_p, *x_p, *wq_p, *wo_p;
    cudaGetSymbolAddress((void**)&qkv_p, g_qkv);
    cudaGetSymbolAddress((void**)&o_p,   g_o);
    cudaGetSymbolAddress((void**)&x_p,   g_x);
    cudaGetSymbolAddress((void**)&wq_p,  g_wq);
    cudaGetSymbolAddress((void**)&wo_p,  g_wo);

    cudaFuncSetAttribute(gemm_tf32_cp<true>,
                         cudaFuncAttributeMaxDynamicSharedMemorySize, GEMM_SMEM_BYTES);
    cudaFuncSetAttribute(gemm_tf32_cp<false>,
                         cudaFuncAttributeMaxDynamicSharedMemorySize, GEMM_SMEM_BYTES);
    cudaFuncSetAttribute(flash_attn_v7,
                         cudaFuncAttributeMaxDynamicSharedMemorySize, FA_SMEM_BYTES);

    // 0) pre-round inputs to tf32 bit patterns
    {
        const int nx = BATCH * CDIM * TDIM;
        const int nq = QKVROWS * CDIM;
        const int nw = CDIM * CDIM;
        round_tf32_kernel<<<nx / 1024, 256>>>(x,    x_p,  nx);
        round_tf32_kernel<<<nq / 1024, 256>>>(Wqkv, wq_p, nq);
        round_tf32_kernel<<<nw / 1024, 256>>>(Wout, wo_p, nw);
    }

    // 1) qkv = Wqkv @ x + bqkv  (output rounded to tf32 bits for flash)
    {
        dim3 grid(TDIM / 128, QKVROWS / 128, BATCH);
        gemm_tf32_cp<true><<<grid, 128, GEMM_SMEM_BYTES>>>(wq_p, x_p, bqkv, qkv_p,
                                                           QKVROWS, TDIM, CDIM);
    }
    // 2) fused flash attention
    {
        dim3 grid(TDIM / FA_TBLK, NHEAD, BATCH);
        flash_attn_v7<<<grid, 256, FA_SMEM_BYTES>>>(mask);
    }
    // 3) out = Wout @ o + bout  (full f32 output)
    {
        dim3 grid(TDIM / 128, CDIM / 128, BATCH);
        gemm_tf32_cp<false><<<grid, 128, GEMM_SMEM_BYTES>>>(wo_p, o_p, bout, out,
                                                            CDIM, TDIM, CDIM);
    }
}

// round 12
// speedup vs baseline: 1.4270x; 1.1720x over previous
#include <cuda_runtime.h>
#include <cuda_fp16.h>
#include <cuda_bf16.h>
#include <cstdint>

#define BATCH 4
#define CDIM  768
#define TDIM  2048
#define NHEAD 12
#define HDIM  64
#define QKVROWS (3 * CDIM)

// ---------------------------------------------------------------------------
// Device scratch
// ---------------------------------------------------------------------------
__device__ float  g_qkv[(size_t)BATCH * QKVROWS * TDIM];  // Q,K tf32-rounded (V region unused)
__device__ __half g_vh [(size_t)BATCH * CDIM * TDIM];     // V in fp16 (B, C, T)
__device__ float  g_o  [(size_t)BATCH * CDIM * TDIM];     // (B, C, T) tf32-rounded
__device__ float  g_x  [(size_t)BATCH * CDIM * TDIM];     // x, tf32-rounded
__device__ float  g_wq [(size_t)QKVROWS * CDIM];          // Wqkv, tf32-rounded
__device__ float  g_wo [(size_t)CDIM * CDIM];             // Wout, tf32-rounded

__device__ __forceinline__ uint32_t f2tf32(float x) {
    uint32_t r;
    asm("cvt.rna.tf32.f32 %0, %1;" : "=r"(r) : "f"(x));
    return r;
}

__device__ __forceinline__ float ex2_approx(float x) {
    float r;
    asm("ex2.approx.f32 %0, %1;" : "=f"(r) : "f"(x));
    return r;
}

// pack two f32 into fp16x2: lo -> lower half, hi -> upper half (RN)
__device__ __forceinline__ uint32_t pack_half2(float lo, float hi) {
    uint32_t r;
    asm("cvt.rn.f16x2.f32 %0, %1, %2;" : "=r"(r) : "f"(hi), "f"(lo));
    return r;
}

__device__ __forceinline__ void mma_tf32(float* c, const uint32_t* a, const uint32_t* b) {
    asm volatile(
        "mma.sync.aligned.m16n8k8.row.col.f32.tf32.tf32.f32 "
        "{%0,%1,%2,%3}, {%4,%5,%6,%7}, {%8,%9}, {%0,%1,%2,%3};\n"
        : "+f"(c[0]), "+f"(c[1]), "+f"(c[2]), "+f"(c[3])
        : "r"(a[0]), "r"(a[1]), "r"(a[2]), "r"(a[3]), "r"(b[0]), "r"(b[1]));
}

__device__ __forceinline__ void mma_fp16(float* c, const uint32_t* a, const uint32_t* b) {
    asm volatile(
        "mma.sync.aligned.m16n8k16.row.col.f32.f16.f16.f32 "
        "{%0,%1,%2,%3}, {%4,%5,%6,%7}, {%8,%9}, {%0,%1,%2,%3};\n"
        : "+f"(c[0]), "+f"(c[1]), "+f"(c[2]), "+f"(c[3])
        : "r"(a[0]), "r"(a[1]), "r"(a[2]), "r"(a[3]), "r"(b[0]), "r"(b[1]));
}

__device__ __forceinline__ uint32_t smem_u32(const void* p) {
    return (uint32_t)__cvta_generic_to_shared(p);
}

__device__ __forceinline__ void cp_async16(uint32_t dst, const void* src) {
    asm volatile("cp.async.cg.shared.global [%0], [%1], 16;\n"
                 :: "r"(dst), "l"(src));
}
#define CP_COMMIT() asm volatile("cp.async.commit_group;\n")

// ---------------------------------------------------------------------------
// Pre-round: out[i] = tf32_rna(in[i]) as f32 bit pattern
// ---------------------------------------------------------------------------
__global__ __launch_bounds__(256)
void round_tf32_kernel(const float* __restrict__ in, float* __restrict__ out, int n)
{
    int i = (blockIdx.x * 256 + threadIdx.x) * 4;
    if (i < n) {
        float4 v = *reinterpret_cast<const float4*>(in + i);
        float4 o;
        o.x = __uint_as_float(f2tf32(v.x));
        o.y = __uint_as_float(f2tf32(v.y));
        o.z = __uint_as_float(f2tf32(v.z));
        o.w = __uint_as_float(f2tf32(v.w));
        *reinterpret_cast<float4*>(out + i) = o;
    }
}

// ---------------------------------------------------------------------------
// tf32 GEMM (R11 shape: 128 thr, 4 warps 2x2, warp tile 64x64, cp.async DB).
// If vroot != null, output rows >= 2C are written as fp16 into vroot.
// ---------------------------------------------------------------------------
#define GA_W (128 * 36)
#define GB_W (32 * 136)
#define GEMM_SMEM_BYTES ((2 * GA_W + 2 * GB_W) * 4)

template<bool ROUND_OUT>
__global__ __launch_bounds__(128, 2)
void gemm_tf32_cp(const float* __restrict__ A,
                  const float* __restrict__ Bmat,
                  const float* __restrict__ bias,
                  float* __restrict__ Cmat,
                  __half* __restrict__ vroot,
                  int M, int N, int K)
{
    extern __shared__ uint32_t gsm[];

    const float* Bp = Bmat + (size_t)blockIdx.z * (size_t)K * N;
    float*       Cp = Cmat + (size_t)blockIdx.z * (size_t)M * N;
    __half*      Vp = vroot ? vroot + (size_t)blockIdx.z * CDIM * TDIM : nullptr;

    const int tid  = threadIdx.x;
    const int lane = tid & 31;
    const int warp = tid >> 5;
    const int g    = lane >> 2;
    const int tig  = lane & 3;
    const int wm   = warp >> 1;
    const int wn   = warp & 1;
    const int row0 = blockIdx.y * 128;
    const int col0 = blockIdx.x * 128;

    const uint32_t sbase = smem_u32(gsm);

    float acc[4][8][4];
    #pragma unroll
    for (int i = 0; i < 4; i++)
        #pragma unroll
        for (int j = 0; j < 8; j++)
            #pragma unroll
            for (int r = 0; r < 4; r++) acc[i][j][r] = 0.0f;

    const int KT = K >> 5;

    auto issue = [&](int s) {
        const int k0 = s * 32;
        const uint32_t abase = sbase + (unsigned)((s & 1) * GA_W) * 4u;
        const uint32_t bbase = sbase + (unsigned)(2 * GA_W + (s & 1) * GB_W) * 4u;
        #pragma unroll
        for (int l = 0; l < 8; l++) {
            int lin = tid + l * 128;
            int m   = lin >> 3;
            int k4  = (lin & 7) * 4;
            cp_async16(abase + (unsigned)(m * 36 + k4) * 4u,
                       A + (size_t)(row0 + m) * K + k0 + k4);
        }
        #pragma unroll
        for (int l = 0; l < 8; l++) {
            int lin = tid + l * 128;
            int k   = lin >> 5;
            int n4  = (lin & 31) * 4;
            cp_async16(bbase + (unsigned)(k * 136 + n4) * 4u,
                       Bp + (size_t)(k0 + k) * N + col0 + n4);
        }
        CP_COMMIT();
    };

    issue(0);
    if (KT > 1) issue(1);

    for (int kt = 0; kt < KT; kt++) {
        const int buf = kt & 1;
        if (kt + 1 < KT) asm volatile("cp.async.wait_group 1;\n");
        else             asm volatile("cp.async.wait_group 0;\n");
        __syncthreads();

        const uint32_t* Ab = gsm + buf * GA_W;
        const uint32_t* Bb = gsm + 2 * GA_W + buf * GB_W;

        #pragma unroll
        for (int kk = 0; kk < 32; kk += 8) {
            uint32_t af[4][4];
            uint32_t bf[8][2];
            #pragma unroll
            for (int mi = 0; mi < 4; mi++) {
                int m = wm * 64 + mi * 16 + g;
                af[mi][0] = Ab[m * 36 + kk + tig];
                af[mi][1] = Ab[(m + 8) * 36 + kk + tig];
                af[mi][2] = Ab[m * 36 + kk + tig + 4];
                af[mi][3] = Ab[(m + 8) * 36 + kk + tig + 4];
            }
            #pragma unroll
            for (int ni = 0; ni < 8; ni++) {
                int n = wn * 64 + ni * 8 + g;
                bf[ni][0] = Bb[(kk + tig) * 136 + n];
                bf[ni][1] = Bb[(kk + tig + 4) * 136 + n];
            }
            #pragma unroll
            for (int mi = 0; mi < 4; mi++)
                #pragma unroll
                for (int ni = 0; ni < 8; ni++)
                    mma_tf32(acc[mi][ni], af[mi], bf[ni]);
        }

        __syncthreads();
        if (kt + 2 < KT) issue(kt + 2);
    }

    #pragma unroll
    for (int mi = 0; mi < 4; mi++) {
        int r0 = row0 + wm * 64 + mi * 16 + g;
        float b0 = bias[r0];
        float b1 = bias[r0 + 8];
        bool vrow = (Vp != nullptr) && (r0 >= 2 * CDIM);
        #pragma unroll
        for (int ni = 0; ni < 8; ni++) {
            int cc = col0 + wn * 64 + ni * 8 + tig * 2;
            float o00 = acc[mi][ni][0] + b0, o01 = acc[mi][ni][1] + b0;
            float o10 = acc[mi][ni][2] + b1, o11 = acc[mi][ni][3] + b1;
            if (vrow) {
                uint32_t w0 = pack_half2(o00, o01);
                uint32_t w1 = pack_half2(o10, o11);
                __half* vp = Vp + (size_t)(r0 - 2 * CDIM) * N + cc;
                *reinterpret_cast<uint32_t*>(vp)                 = w0;
                *reinterpret_cast<uint32_t*>(vp + (size_t)8 * N) = w1;
            } else {
                if (ROUND_OUT) {
                    o00 = __uint_as_float(f2tf32(o00));
                    o01 = __uint_as_float(f2tf32(o01));
                    o10 = __uint_as_float(f2tf32(o10));
                    o11 = __uint_as_float(f2tf32(o11));
                }
                *reinterpret_cast<float2*>(Cp + (size_t)r0 * N + cc)       = make_float2(o00, o01);
                *reinterpret_cast<float2*>(Cp + (size_t)(r0 + 8) * N + cc) = make_float2(o10, o11);
            }
        }
    }
}

// ---------------------------------------------------------------------------
// Flash attention v10: fp16 PV path (R9 structure, fp16 numerics).
//  - QK^T in tf32 (k8), P packed to fp16x2 (RN) right after exp
//  - C-frag(m16n8k8) layout == A-frag(m16n8k16) layout -> ZERO shuffles
//  - V staged as fp16 ([d][s/2] words, pitch 36), PV in fp16 k16
//  - 3-stage cp.async ring; Q frags in registers; ex2-folded softmax
// grid (T/256, H, B), 256 threads, warp tile 32t x 64s / 32t x 64d.
// ---------------------------------------------------------------------------
#define KS_P 72
#define VW_P 36
#define FA_TBLK 256
#define KSTG (64 * KS_P)
#define VSTG (64 * VW_P)
#define FA_NCHUNK (TDIM / 64)
#define FA_SMEM_WORDS (3 * KSTG + 3 * VSTG + TDIM)
#define FA_SMEM_BYTES (FA_SMEM_WORDS * 4)
#define LOG2E 1.44269504088896340736f

__global__ __launch_bounds__(256, 1)
void flash_attn_v10(const int* __restrict__ mask)
{
    extern __shared__ uint32_t fsm[];
    uint32_t* Ks      = fsm;                       // 3 stages [d][s] f32-tf32, pitch 72
    uint32_t* Vs      = Ks + 3 * KSTG;             // 3 stages [d][s/2] fp16x2, pitch 36
    float*    maskAll = (float*)(Vs + 3 * VSTG);   // 2048 biases (pre-scaled by log2e)

    const int b    = blockIdx.z;
    const int h    = blockIdx.y;
    const int tt   = blockIdx.x;
    const int tid  = threadIdx.x;
    const int lane = tid & 31;
    const int warp = tid >> 5;
    const int g    = lane >> 2;
    const int tig  = lane & 3;
    const int tw   = warp * 32;

    const size_t base = (size_t)b * QKVROWS * TDIM;
    const float*  qptr = g_qkv + base + (size_t)(h * HDIM) * TDIM + tt * FA_TBLK + tw;
    const float*  kptr = g_qkv + base + (size_t)(CDIM + h * HDIM) * TDIM;
    const __half* vptr = g_vh + (size_t)b * CDIM * TDIM + (size_t)(h * HDIM) * TDIM;

    const uint32_t kbase0 = smem_u32(Ks);
    const uint32_t vbase0 = smem_u32(Vs);

    auto issue = [&](int ch) {
        const uint32_t kb = kbase0 + (unsigned)((ch % 3) * KSTG) * 4u;
        const uint32_t vb = vbase0 + (unsigned)((ch % 3) * VSTG) * 4u;
        const int s0 = ch * 64;
        #pragma unroll
        for (int l = 0; l < 4; l++) {          // K: 64 d x 16 segs of 16B
            int lin = tid + l * 256;
            int d   = lin >> 4;
            int s4  = (lin & 15) * 4;
            cp_async16(kb + (unsigned)(d * KS_P + s4) * 4u,
                       kptr + (size_t)d * TDIM + s0 + s4);
        }
        #pragma unroll
        for (int l = 0; l < 2; l++) {          // V fp16: 64 d x 8 segs of 16B
            int lin = tid + l * 256;
            int d   = lin >> 3;
            int seg = lin & 7;
            cp_async16(vb + (unsigned)(d * VW_P * 4 + seg * 16),
                       vptr + (size_t)d * TDIM + s0 + seg * 8);
        }
        CP_COMMIT();
    };

    issue(0); issue(1); issue(2);

    // Q fragments in registers, loaded once (qkv Q rows tf32-rounded bits).
    uint32_t Qf[2][8][4];
    #pragma unroll
    for (int mi = 0; mi < 2; mi++)
        #pragma unroll
        for (int kk = 0; kk < 8; kk++) {
            const float* qp = qptr + (size_t)(kk * 8 + tig) * TDIM + mi * 16 + g;
            Qf[mi][kk][0] = __float_as_uint(qp[0]);
            Qf[mi][kk][1] = __float_as_uint(qp[8]);
            Qf[mi][kk][2] = __float_as_uint(qp[4 * TDIM]);
            Qf[mi][kk][3] = __float_as_uint(qp[4 * TDIM + 8]);
        }

    // Whole-row mask biases, pre-scaled by log2(e)
    for (int i = tid; i < TDIM; i += 256)
        maskAll[i] = (mask[(size_t)b * TDIM + i] == 0) ? (-10000.0f * LOG2E) : 0.0f;

    float accO[2][8][4];
    #pragma unroll
    for (int mi = 0; mi < 2; mi++)
        #pragma unroll
        for (int ni = 0; ni < 8; ni++)
            #pragma unroll
            for (int r = 0; r < 4; r++) accO[mi][ni][r] = 0.0f;

    float rowl[2][2] = {{0.0f, 0.0f}, {0.0f, 0.0f}};

    const float sc2 = 0.125f * LOG2E;

    for (int kt = 0; kt < FA_NCHUNK; kt++) {
        if      (kt + 2 < FA_NCHUNK) asm volatile("cp.async.wait_group 2;\n");
        else if (kt + 1 < FA_NCHUNK) asm volatile("cp.async.wait_group 1;\n");
        else                         asm volatile("cp.async.wait_group 0;\n");
        __syncthreads();

        const uint32_t* Kb = Ks + (kt % 3) * KSTG;
        const uint32_t* Vw = Vs + (kt % 3) * VSTG;
        const float*    mb = maskAll + kt * 64;

        // ---- S = Q K^T (tf32), warp tile 32t x 64s ----
        float sacc[2][8][4];
        #pragma unroll
        for (int mi = 0; mi < 2; mi++)
            #pragma unroll
            for (int ni = 0; ni < 8; ni++)
                #pragma unroll
                for (int r = 0; r < 4; r++) sacc[mi][ni][r] = 0.0f;

        #pragma unroll
        for (int kk = 0; kk < 8; kk++) {
            uint32_t bf[8][2];
            #pragma unroll
            for (int ni = 0; ni < 8; ni++) {
                bf[ni][0] = Kb[(kk * 8 + tig) * KS_P + ni * 8 + g];
                bf[ni][1] = Kb[(kk * 8 + tig + 4) * KS_P + ni * 8 + g];
            }
            #pragma unroll
            for (int mi = 0; mi < 2; mi++)
                #pragma unroll
                for (int ni = 0; ni < 8; ni++)
                    mma_tf32(sacc[mi][ni], Qf[mi][kk], bf[ni]);
        }

        // ---- softmax numerators, pack P to fp16x2 (s-pairs) ----
        uint32_t pp[2][8][2];
        float rs[2][2] = {{0.0f, 0.0f}, {0.0f, 0.0f}};
        #pragma unroll
        for (int mi = 0; mi < 2; mi++)
            #pragma unroll
            for (int ni = 0; ni < 8; ni++) {
                int sb = ni * 8 + tig * 2;
                float b0 = mb[sb], b1 = mb[sb + 1];
                float p0 = ex2_approx(fmaf(sacc[mi][ni][0], sc2, b0));
                float p1 = ex2_approx(fmaf(sacc[mi][ni][1], sc2, b1));
                float p2 = ex2_approx(fmaf(sacc[mi][ni][2], sc2, b0));
                float p3 = ex2_approx(fmaf(sacc[mi][ni][3], sc2, b1));
                rs[mi][0] += p0 + p1;
                rs[mi][1] += p2 + p3;
                pp[mi][ni][0] = pack_half2(p0, p1);   // row g,   s-pair
                pp[mi][ni][1] = pack_half2(p2, p3);   // row g+8, s-pair
            }
        #pragma unroll
        for (int mi = 0; mi < 2; mi++)
            #pragma unroll
            for (int j = 0; j < 2; j++) {
                float r = rs[mi][j];
                r += __shfl_xor_sync(0xffffffffu, r, 1);
                r += __shfl_xor_sync(0xffffffffu, r, 2);
                rowl[mi][j] += r;
            }

        // ---- O += P V (fp16 m16n8k16), 4 k-blocks of 16 s ----
        #pragma unroll
        for (int kb = 0; kb < 4; kb++) {
            uint32_t bf[8][2];
            #pragma unroll
            for (int ni = 0; ni < 8; ni++) {
                bf[ni][0] = Vw[(ni * 8 + g) * VW_P + kb * 8 + tig];
                bf[ni][1] = Vw[(ni * 8 + g) * VW_P + kb * 8 + 4 + tig];
            }
            #pragma unroll
            for (int mi = 0; mi < 2; mi++) {
                uint32_t a[4] = { pp[mi][2 * kb][0],     pp[mi][2 * kb][1],
                                  pp[mi][2 * kb + 1][0], pp[mi][2 * kb + 1][1] };
                #pragma unroll
                for (int ni = 0; ni < 8; ni++)
                    mma_fp16(accO[mi][ni], a, bf[ni]);
            }
        }

        __syncthreads();
        if (kt + 3 < FA_NCHUNK) issue(kt + 3);
    }

    // ---- epilogue: normalize, round to tf32 bits (GEMM3 eats raw) ----
    float* optr = g_o + (size_t)b * CDIM * TDIM + (size_t)(h * HDIM) * TDIM
                + tt * FA_TBLK + tw;
    #pragma unroll
    for (int mi = 0; mi < 2; mi++) {
        float il0 = 1.0f / rowl[mi][0];
        float il1 = 1.0f / rowl[mi][1];
        #pragma unroll
        for (int ni = 0; ni < 8; ni++) {
            int d = ni * 8 + tig * 2;
            float* op = optr + (size_t)d * TDIM + mi * 16 + g;
            op[0]        = __uint_as_float(f2tf32(accO[mi][ni][0] * il0));
            op[TDIM]     = __uint_as_float(f2tf32(accO[mi][ni][1] * il0));
            op[8]        = __uint_as_float(f2tf32(accO[mi][ni][2] * il1));
            op[TDIM + 8] = __uint_as_float(f2tf32(accO[mi][ni][3] * il1));
        }
    }
}

// ---------------------------------------------------------------------------
// kernel_launch (single stream, graph-safe)
// ---------------------------------------------------------------------------
extern "C" void kernel_launch(void* const* d_in, const int* in_sizes, int n_in,
                              void* d_out, int out_size)
{
    const float* x    = (const float*)d_in[0];
    const int*   mask = (const int*)  d_in[1];
    const float* Wqkv = (const float*)d_in[2];
    const float* bqkv = (const float*)d_in[3];
    const float* Wout = (const float*)d_in[4];
    const float* bout = (const float*)d_in[5];
    float*       out  = (float*)d_out;

    float *qkv_p, *o_p, *x_p, *wq_p, *wo_p;
    __half* vh_p;
    cudaGetSymbolAddress((void**)&qkv_p, g_qkv);
    cudaGetSymbolAddress((void**)&o_p,   g_o);
    cudaGetSymbolAddress((void**)&x_p,   g_x);
    cudaGetSymbolAddress((void**)&wq_p,  g_wq);
    cudaGetSymbolAddress((void**)&wo_p,  g_wo);
    cudaGetSymbolAddress((void**)&vh_p,  g_vh);

    cudaFuncSetAttribute(gemm_tf32_cp<true>,
                         cudaFuncAttributeMaxDynamicSharedMemorySize, GEMM_SMEM_BYTES);
    cudaFuncSetAttribute(gemm_tf32_cp<false>,
                         cudaFuncAttributeMaxDynamicSharedMemorySize, GEMM_SMEM_BYTES);
    cudaFuncSetAttribute(flash_attn_v10,
                         cudaFuncAttributeMaxDynamicSharedMemorySize, FA_SMEM_BYTES);

    // 0) pre-round inputs to tf32 bit patterns
    {
        const int nx = BATCH * CDIM * TDIM;
        const int nq = QKVROWS * CDIM;
        const int nw = CDIM * CDIM;
        round_tf32_kernel<<<nx / 1024, 256>>>(x,    x_p,  nx);
        round_tf32_kernel<<<nq / 1024, 256>>>(Wqkv, wq_p, nq);
        round_tf32_kernel<<<nw / 1024, 256>>>(Wout, wo_p, nw);
    }

    // 1) qkv = Wqkv @ x + bqkv  (Q,K tf32-rounded f32; V rows -> fp16 buffer)
    {
        dim3 grid(TDIM / 128, QKVROWS / 128, BATCH);
        gemm_tf32_cp<true><<<grid, 128, GEMM_SMEM_BYTES>>>(
            wq_p, x_p, bqkv, qkv_p, vh_p, QKVROWS, TDIM, CDIM);
    }
    // 2) fused flash attention (fp16 PV)
    {
        dim3 grid(TDIM / FA_TBLK, NHEAD, BATCH);
        flash_attn_v10<<<grid, 256, FA_SMEM_BYTES>>>(mask);
    }
    // 3) out = Wout @ o + bout  (full f32 output)
    {
        dim3 grid(TDIM / 128, CDIM / 128, BATCH);
        gemm_tf32_cp<false><<<grid, 128, GEMM_SMEM_BYTES>>>(
            wo_p, o_p, bout, out, nullptr, CDIM, TDIM, CDIM);
    }
}

// round 13
// speedup vs baseline: 1.8329x; 1.2844x over previous
#include <cuda_runtime.h>
#include <cuda_fp16.h>
#include <cuda_bf16.h>
#include <cstdint>

#define BATCH 4
#define CDIM  768
#define TDIM  2048
#define NHEAD 12
#define HDIM  64
#define QKVROWS (3 * CDIM)

// ---------------------------------------------------------------------------
// Device scratch
// ---------------------------------------------------------------------------
__device__ float    g_qkv[(size_t)BATCH * QKVROWS * TDIM];      // Q,K tf32-rounded f32 (V region unused)
__device__ __half   g_vh [(size_t)BATCH * CDIM * TDIM];         // V fp16 (B, C, T)
__device__ uint32_t g_oh [(size_t)BATCH * (CDIM/2) * TDIM];     // o, fp16x2 k-pair words (B, C/2, T)
__device__ uint32_t g_xh [(size_t)BATCH * (CDIM/2) * TDIM];     // x, fp16x2 k-pair words
__device__ __half   g_wqh[(size_t)QKVROWS * CDIM];              // Wqkv fp16 [M][K]
__device__ __half   g_woh[(size_t)CDIM * CDIM];                 // Wout fp16 [M][K]

__device__ __forceinline__ uint32_t f2tf32(float x) {
    uint32_t r;
    asm("cvt.rna.tf32.f32 %0, %1;" : "=r"(r) : "f"(x));
    return r;
}

__device__ __forceinline__ float ex2_approx(float x) {
    float r;
    asm("ex2.approx.f32 %0, %1;" : "=f"(r) : "f"(x));
    return r;
}

// pack two f32 into fp16x2: lo -> lower half, hi -> upper half (RN)
__device__ __forceinline__ uint32_t pack_half2(float lo, float hi) {
    uint32_t r;
    asm("cvt.rn.f16x2.f32 %0, %1, %2;" : "=r"(r) : "f"(hi), "f"(lo));
    return r;
}

__device__ __forceinline__ void mma_tf32(float* c, const uint32_t* a, const uint32_t* b) {
    asm volatile(
        "mma.sync.aligned.m16n8k8.row.col.f32.tf32.tf32.f32 "
        "{%0,%1,%2,%3}, {%4,%5,%6,%7}, {%8,%9}, {%0,%1,%2,%3};\n"
        : "+f"(c[0]), "+f"(c[1]), "+f"(c[2]), "+f"(c[3])
        : "r"(a[0]), "r"(a[1]), "r"(a[2]), "r"(a[3]), "r"(b[0]), "r"(b[1]));
}

__device__ __forceinline__ void mma_fp16(float* c, const uint32_t* a, const uint32_t* b) {
    asm volatile(
        "mma.sync.aligned.m16n8k16.row.col.f32.f16.f16.f32 "
        "{%0,%1,%2,%3}, {%4,%5,%6,%7}, {%8,%9}, {%0,%1,%2,%3};\n"
        : "+f"(c[0]), "+f"(c[1]), "+f"(c[2]), "+f"(c[3])
        : "r"(a[0]), "r"(a[1]), "r"(a[2]), "r"(a[3]), "r"(b[0]), "r"(b[1]));
}

__device__ __forceinline__ uint32_t smem_u32(const void* p) {
    return (uint32_t)__cvta_generic_to_shared(p);
}

__device__ __forceinline__ void cp_async16(uint32_t dst, const void* src) {
    asm volatile("cp.async.cg.shared.global [%0], [%1], 16;\n"
                 :: "r"(dst), "l"(src));
}
#define CP_COMMIT() asm volatile("cp.async.commit_group;\n")

// ---------------------------------------------------------------------------
// Pack kernels
// ---------------------------------------------------------------------------
// weights: f32 [M][K] -> fp16 [M][K] (k-pairs contiguous)
__global__ __launch_bounds__(256)
void pack_w_kernel(const float* __restrict__ in, __half* __restrict__ out, int n)
{
    int i = (blockIdx.x * 256 + threadIdx.x) * 4;
    if (i < n) {
        float4 v = *reinterpret_cast<const float4*>(in + i);
        uint2 w = make_uint2(pack_half2(v.x, v.y), pack_half2(v.z, v.w));
        *reinterpret_cast<uint2*>(out + i) = w;
    }
}

// x: f32 (B,C,T) -> fp16x2 k-pair words (B, C/2, T): word(kp,t) = (x[2kp][t], x[2kp+1][t])
__global__ __launch_bounds__(256)
void pack_x_kernel(const float* __restrict__ x, uint32_t* __restrict__ xh)
{
    const int WPB = (CDIM / 2) * (TDIM / 4);          // word4 units per batch
    int idx = blockIdx.x * 256 + threadIdx.x;
    int b   = idx / WPB;
    int r   = idx % WPB;
    int kp  = r / (TDIM / 4);
    int t4  = (r % (TDIM / 4)) * 4;
    const float* r0 = x + ((size_t)b * CDIM + 2 * kp) * TDIM + t4;
    float4 a = *reinterpret_cast<const float4*>(r0);
    float4 c = *reinterpret_cast<const float4*>(r0 + TDIM);
    uint4 w = make_uint4(pack_half2(a.x, c.x), pack_half2(a.y, c.y),
                         pack_half2(a.z, c.z), pack_half2(a.w, c.w));
    *reinterpret_cast<uint4*>(xh + ((size_t)b * (CDIM / 2) + kp) * TDIM + t4) = w;
}

// ---------------------------------------------------------------------------
// fp16 GEMM (f32 accum): 128x128 block tile, 128 thr (2x2 warps, 64x64 warp
// tile), kTile=32 (2 x k16 MMA steps), cp.async double buffered.
// A: fp16 [M][K]. B: fp16x2 k-pair words [K/2][N] (batch stride (K/2)*N).
// MODE 0: C = f32 out + bias. MODE 1 (qkv): rows < 2C -> tf32-rounded f32 to
// Cmat; rows >= 2C -> fp16 to vroot.
// ---------------------------------------------------------------------------
#define GA_WW (128 * 20)
#define GB_WW (16 * 136)
#define GEMM_SMEM_BYTES ((2 * GA_WW + 2 * GB_WW) * 4)

template<int MODE>
__global__ __launch_bounds__(128, 2)
void gemm_fp16_cp(const __half* __restrict__ Ah,
                  const uint32_t* __restrict__ Bw,
                  const float* __restrict__ bias,
                  float* __restrict__ Cmat,
                  __half* __restrict__ vroot,
                  int M, int N, int K)
{
    extern __shared__ uint32_t gsm[];

    const uint32_t* Bp = Bw + (size_t)blockIdx.z * (size_t)(K / 2) * N;
    float*          Cp = Cmat + (size_t)blockIdx.z * (size_t)M * N;
    __half*         Vp = (MODE == 1) ? vroot + (size_t)blockIdx.z * CDIM * TDIM : nullptr;

    const int tid  = threadIdx.x;
    const int lane = tid & 31;
    const int warp = tid >> 5;
    const int g    = lane >> 2;
    const int tig  = lane & 3;
    const int wm   = warp >> 1;
    const int wn   = warp & 1;
    const int row0 = blockIdx.y * 128;
    const int col0 = blockIdx.x * 128;

    const uint32_t sbase = smem_u32(gsm);

    float acc[4][8][4];
    #pragma unroll
    for (int i = 0; i < 4; i++)
        #pragma unroll
        for (int j = 0; j < 8; j++)
            #pragma unroll
            for (int r = 0; r < 4; r++) acc[i][j][r] = 0.0f;

    const int KT = K >> 5;

    auto issue = [&](int s) {
        const int k0 = s * 32;                 // in fp16 elements
        const uint32_t abase = sbase + (unsigned)((s & 1) * GA_WW) * 4u;
        const uint32_t bbase = sbase + (unsigned)(2 * GA_WW + (s & 1) * GB_WW) * 4u;
        #pragma unroll
        for (int l = 0; l < 4; l++) {          // A: 128m x 16kw words
            int lin = tid + l * 128;
            int m   = lin >> 2;
            int kw4 = (lin & 3) * 4;
            cp_async16(abase + (unsigned)(m * 20 + kw4) * 4u,
                       Ah + (size_t)(row0 + m) * K + k0 + kw4 * 2);
        }
        #pragma unroll
        for (int l = 0; l < 4; l++) {          // B: 16kw x 128n words
            int lin = tid + l * 128;
            int kw  = lin >> 5;
            int n4  = (lin & 31) * 4;
            cp_async16(bbase + (unsigned)(kw * 136 + n4) * 4u,
                       Bp + (size_t)(k0 / 2 + kw) * N + col0 + n4);
        }
        CP_COMMIT();
    };

    issue(0);
    if (KT > 1) issue(1);

    for (int kt = 0; kt < KT; kt++) {
        const int buf = kt & 1;
        if (kt + 1 < KT) asm volatile("cp.async.wait_group 1;\n");
        else             asm volatile("cp.async.wait_group 0;\n");
        __syncthreads();

        const uint32_t* Ab = gsm + buf * GA_WW;
        const uint32_t* Bb = gsm + 2 * GA_WW + buf * GB_WW;

        #pragma unroll
        for (int ks = 0; ks < 2; ks++) {       // two k16 steps per 32-k tile
            const int kwb = ks * 8;
            uint32_t af[4][4];
            uint32_t bf[8][2];
            #pragma unroll
            for (int mi = 0; mi < 4; mi++) {
                int m = wm * 64 + mi * 16 + g;
                af[mi][0] = Ab[m * 20 + kwb + tig];
                af[mi][1] = Ab[(m + 8) * 20 + kwb + tig];
                af[mi][2] = Ab[m * 20 + kwb + tig + 4];
                af[mi][3] = Ab[(m + 8) * 20 + kwb + tig + 4];
            }
            #pragma unroll
            for (int ni = 0; ni < 8; ni++) {
                int n = wn * 64 + ni * 8 + g;
                bf[ni][0] = Bb[(kwb + tig) * 136 + n];
                bf[ni][1] = Bb[(kwb + tig + 4) * 136 + n];
            }
            #pragma unroll
            for (int mi = 0; mi < 4; mi++)
                #pragma unroll
                for (int ni = 0; ni < 8; ni++)
                    mma_fp16(acc[mi][ni], af[mi], bf[ni]);
        }

        __syncthreads();
        if (kt + 2 < KT) issue(kt + 2);
    }

    #pragma unroll
    for (int mi = 0; mi < 4; mi++) {
        int r0 = row0 + wm * 64 + mi * 16 + g;
        float b0 = bias[r0];
        float b1 = bias[r0 + 8];
        bool vrow = (MODE == 1) && (r0 >= 2 * CDIM);
        #pragma unroll
        for (int ni = 0; ni < 8; ni++) {
            int cc = col0 + wn * 64 + ni * 8 + tig * 2;
            float o00 = acc[mi][ni][0] + b0, o01 = acc[mi][ni][1] + b0;
            float o10 = acc[mi][ni][2] + b1, o11 = acc[mi][ni][3] + b1;
            if (MODE == 1) {
                if (vrow) {
                    __half* vp = Vp + (size_t)(r0 - 2 * CDIM) * N + cc;
                    *reinterpret_cast<uint32_t*>(vp)                 = pack_half2(o00, o01);
                    *reinterpret_cast<uint32_t*>(vp + (size_t)8 * N) = pack_half2(o10, o11);
                } else {
                    o00 = __uint_as_float(f2tf32(o00));
                    o01 = __uint_as_float(f2tf32(o01));
                    o10 = __uint_as_float(f2tf32(o10));
                    o11 = __uint_as_float(f2tf32(o11));
                    *reinterpret_cast<float2*>(Cp + (size_t)r0 * N + cc)       = make_float2(o00, o01);
                    *reinterpret_cast<float2*>(Cp + (size_t)(r0 + 8) * N + cc) = make_float2(o10, o11);
                }
            } else {
                *reinterpret_cast<float2*>(Cp + (size_t)r0 * N + cc)       = make_float2(o00, o01);
                *reinterpret_cast<float2*>(Cp + (size_t)(r0 + 8) * N + cc) = make_float2(o10, o11);
            }
        }
    }
}

// ---------------------------------------------------------------------------
// Flash attention v10 (R12 core: tf32 QK^T, fp16 PV, zero-shuffle P relayout).
// Epilogue now writes o as fp16x2 k-pair words (GEMM3's B operand directly).
// grid (T/256, H, B), 256 threads, warp tile 32t x 64s / 32t x 64d.
// ---------------------------------------------------------------------------
#define KS_P 72
#define VW_P 36
#define FA_TBLK 256
#define KSTG (64 * KS_P)
#define VSTG (64 * VW_P)
#define FA_NCHUNK (TDIM / 64)
#define FA_SMEM_WORDS (3 * KSTG + 3 * VSTG + TDIM)
#define FA_SMEM_BYTES (FA_SMEM_WORDS * 4)
#define LOG2E 1.44269504088896340736f

__global__ __launch_bounds__(256, 1)
void flash_attn_v10(const int* __restrict__ mask)
{
    extern __shared__ uint32_t fsm[];
    uint32_t* Ks      = fsm;                       // 3 stages [d][s] f32-tf32, pitch 72
    uint32_t* Vs      = Ks + 3 * KSTG;             // 3 stages [d][s/2] fp16x2, pitch 36
    float*    maskAll = (float*)(Vs + 3 * VSTG);   // 2048 biases (pre-scaled by log2e)

    const int b    = blockIdx.z;
    const int h    = blockIdx.y;
    const int tt   = blockIdx.x;
    const int tid  = threadIdx.x;
    const int lane = tid & 31;
    const int warp = tid >> 5;
    const int g    = lane >> 2;
    const int tig  = lane & 3;
    const int tw   = warp * 32;

    const size_t base = (size_t)b * QKVROWS * TDIM;
    const float*  qptr = g_qkv + base + (size_t)(h * HDIM) * TDIM + tt * FA_TBLK + tw;
    const float*  kptr = g_qkv + base + (size_t)(CDIM + h * HDIM) * TDIM;
    const __half* vptr = g_vh + (size_t)b * CDIM * TDIM + (size_t)(h * HDIM) * TDIM;

    const uint32_t kbase0 = smem_u32(Ks);
    const uint32_t vbase0 = smem_u32(Vs);

    auto issue = [&](int ch) {
        const uint32_t kb = kbase0 + (unsigned)((ch % 3) * KSTG) * 4u;
        const uint32_t vb = vbase0 + (unsigned)((ch % 3) * VSTG) * 4u;
        const int s0 = ch * 64;
        #pragma unroll
        for (int l = 0; l < 4; l++) {
            int lin = tid + l * 256;
            int d   = lin >> 4;
            int s4  = (lin & 15) * 4;
            cp_async16(kb + (unsigned)(d * KS_P + s4) * 4u,
                       kptr + (size_t)d * TDIM + s0 + s4);
        }
        #pragma unroll
        for (int l = 0; l < 2; l++) {
            int lin = tid + l * 256;
            int d   = lin >> 3;
            int seg = lin & 7;
            cp_async16(vb + (unsigned)(d * VW_P * 4 + seg * 16),
                       vptr + (size_t)d * TDIM + s0 + seg * 8);
        }
        CP_COMMIT();
    };

    issue(0); issue(1); issue(2);

    // Q fragments in registers, loaded once (Q rows tf32-rounded bits).
    uint32_t Qf[2][8][4];
    #pragma unroll
    for (int mi = 0; mi < 2; mi++)
        #pragma unroll
        for (int kk = 0; kk < 8; kk++) {
            const float* qp = qptr + (size_t)(kk * 8 + tig) * TDIM + mi * 16 + g;
            Qf[mi][kk][0] = __float_as_uint(qp[0]);
            Qf[mi][kk][1] = __float_as_uint(qp[8]);
            Qf[mi][kk][2] = __float_as_uint(qp[4 * TDIM]);
            Qf[mi][kk][3] = __float_as_uint(qp[4 * TDIM + 8]);
        }

    for (int i = tid; i < TDIM; i += 256)
        maskAll[i] = (mask[(size_t)b * TDIM + i] == 0) ? (-10000.0f * LOG2E) : 0.0f;

    float accO[2][8][4];
    #pragma unroll
    for (int mi = 0; mi < 2; mi++)
        #pragma unroll
        for (int ni = 0; ni < 8; ni++)
            #pragma unroll
            for (int r = 0; r < 4; r++) accO[mi][ni][r] = 0.0f;

    float rowl[2][2] = {{0.0f, 0.0f}, {0.0f, 0.0f}};

    const float sc2 = 0.125f * LOG2E;

    for (int kt = 0; kt < FA_NCHUNK; kt++) {
        if      (kt + 2 < FA_NCHUNK) asm volatile("cp.async.wait_group 2;\n");
        else if (kt + 1 < FA_NCHUNK) asm volatile("cp.async.wait_group 1;\n");
        else                         asm volatile("cp.async.wait_group 0;\n");
        __syncthreads();

        const uint32_t* Kb = Ks + (kt % 3) * KSTG;
        const uint32_t* Vw = Vs + (kt % 3) * VSTG;
        const float*    mb = maskAll + kt * 64;

        float sacc[2][8][4];
        #pragma unroll
        for (int mi = 0; mi < 2; mi++)
            #pragma unroll
            for (int ni = 0; ni < 8; ni++)
                #pragma unroll
                for (int r = 0; r < 4; r++) sacc[mi][ni][r] = 0.0f;

        #pragma unroll
        for (int kk = 0; kk < 8; kk++) {
            uint32_t bf[8][2];
            #pragma unroll
            for (int ni = 0; ni < 8; ni++) {
                bf[ni][0] = Kb[(kk * 8 + tig) * KS_P + ni * 8 + g];
                bf[ni][1] = Kb[(kk * 8 + tig + 4) * KS_P + ni * 8 + g];
            }
            #pragma unroll
            for (int mi = 0; mi < 2; mi++)
                #pragma unroll
                for (int ni = 0; ni < 8; ni++)
                    mma_tf32(sacc[mi][ni], Qf[mi][kk], bf[ni]);
        }

        uint32_t pp[2][8][2];
        float rs[2][2] = {{0.0f, 0.0f}, {0.0f, 0.0f}};
        #pragma unroll
        for (int mi = 0; mi < 2; mi++)
            #pragma unroll
            for (int ni = 0; ni < 8; ni++) {
                int sb = ni * 8 + tig * 2;
                float b0 = mb[sb], b1 = mb[sb + 1];
                float p0 = ex2_approx(fmaf(sacc[mi][ni][0], sc2, b0));
                float p1 = ex2_approx(fmaf(sacc[mi][ni][1], sc2, b1));
                float p2 = ex2_approx(fmaf(sacc[mi][ni][2], sc2, b0));
                float p3 = ex2_approx(fmaf(sacc[mi][ni][3], sc2, b1));
                rs[mi][0] += p0 + p1;
                rs[mi][1] += p2 + p3;
                pp[mi][ni][0] = pack_half2(p0, p1);
                pp[mi][ni][1] = pack_half2(p2, p3);
            }
        #pragma unroll
        for (int mi = 0; mi < 2; mi++)
            #pragma unroll
            for (int j = 0; j < 2; j++) {
                float r = rs[mi][j];
                r += __shfl_xor_sync(0xffffffffu, r, 1);
                r += __shfl_xor_sync(0xffffffffu, r, 2);
                rowl[mi][j] += r;
            }

        #pragma unroll
        for (int kb = 0; kb < 4; kb++) {
            uint32_t bf[8][2];
            #pragma unroll
            for (int ni = 0; ni < 8; ni++) {
                bf[ni][0] = Vw[(ni * 8 + g) * VW_P + kb * 8 + tig];
                bf[ni][1] = Vw[(ni * 8 + g) * VW_P + kb * 8 + 4 + tig];
            }
            #pragma unroll
            for (int mi = 0; mi < 2; mi++) {
                uint32_t a[4] = { pp[mi][2 * kb][0],     pp[mi][2 * kb][1],
                                  pp[mi][2 * kb + 1][0], pp[mi][2 * kb + 1][1] };
                #pragma unroll
                for (int ni = 0; ni < 8; ni++)
                    mma_fp16(accO[mi][ni], a, bf[ni]);
            }
        }

        __syncthreads();
        if (kt + 3 < FA_NCHUNK) issue(kt + 3);
    }

    // ---- epilogue: normalize, write o as fp16x2 k-pair words ----
    // thread holds (d, d+1) with d = ni*8 + tig*2 -> word row dw = d/2.
    uint32_t* ohp = g_oh + (size_t)b * (CDIM / 2) * TDIM
                  + (size_t)(h * (HDIM / 2)) * TDIM + tt * FA_TBLK + tw;
    #pragma unroll
    for (int mi = 0; mi < 2; mi++) {
        float il0 = 1.0f / rowl[mi][0];
        float il1 = 1.0f / rowl[mi][1];
        #pragma unroll
        for (int ni = 0; ni < 8; ni++) {
            int dw = ni * 4 + tig;
            uint32_t* op = ohp + (size_t)dw * TDIM + mi * 16 + g;
            op[0] = pack_half2(accO[mi][ni][0] * il0, accO[mi][ni][1] * il0);
            op[8] = pack_half2(accO[mi][ni][2] * il1, accO[mi][ni][3] * il1);
        }
    }
}

// ---------------------------------------------------------------------------
// kernel_launch (single stream, graph-safe)
// ---------------------------------------------------------------------------
extern "C" void kernel_launch(void* const* d_in, const int* in_sizes, int n_in,
                              void* d_out, int out_size)
{
    const float* x    = (const float*)d_in[0];
    const int*   mask = (const int*)  d_in[1];
    const float* Wqkv = (const float*)d_in[2];
    const float* bqkv = (const float*)d_in[3];
    const float* Wout = (const float*)d_in[4];
    const float* bout = (const float*)d_in[5];
    float*       out  = (float*)d_out;

    float *qkv_p;
    __half *vh_p, *wqh_p, *woh_p;
    uint32_t *oh_p, *xh_p;
    cudaGetSymbolAddress((void**)&qkv_p, g_qkv);
    cudaGetSymbolAddress((void**)&vh_p,  g_vh);
    cudaGetSymbolAddress((void**)&oh_p,  g_oh);
    cudaGetSymbolAddress((void**)&xh_p,  g_xh);
    cudaGetSymbolAddress((void**)&wqh_p, g_wqh);
    cudaGetSymbolAddress((void**)&woh_p, g_woh);

    cudaFuncSetAttribute(gemm_fp16_cp<0>,
                         cudaFuncAttributeMaxDynamicSharedMemorySize, GEMM_SMEM_BYTES);
    cudaFuncSetAttribute(gemm_fp16_cp<1>,
                         cudaFuncAttributeMaxDynamicSharedMemorySize, GEMM_SMEM_BYTES);
    cudaFuncSetAttribute(flash_attn_v10,
                         cudaFuncAttributeMaxDynamicSharedMemorySize, FA_SMEM_BYTES);

    // 0) pack inputs to fp16
    {
        const int nq = QKVROWS * CDIM;
        const int nw = CDIM * CDIM;
        const int nxw4 = BATCH * (CDIM / 2) * (TDIM / 4);    // 786432
        pack_w_kernel<<<nq / 1024, 256>>>(Wqkv, wqh_p, nq);
        pack_w_kernel<<<nw / 1024, 256>>>(Wout, woh_p, nw);
        pack_x_kernel<<<nxw4 / 256, 256>>>(x, xh_p);
    }

    // 1) qkv = Wqkv @ x + bqkv  (Q,K -> tf32-rounded f32; V -> fp16)
    {
        dim3 grid(TDIM / 128, QKVROWS / 128, BATCH);
        gemm_fp16_cp<1><<<grid, 128, GEMM_SMEM_BYTES>>>(
            wqh_p, xh_p, bqkv, qkv_p, vh_p, QKVROWS, TDIM, CDIM);
    }
    // 2) fused flash attention (tf32 QK^T, fp16 PV, packed fp16 o out)
    {
        dim3 grid(TDIM / FA_TBLK, NHEAD, BATCH);
        flash_attn_v10<<<grid, 256, FA_SMEM_BYTES>>>(mask);
    }
    // 3) out = Wout @ o + bout  (fp16 GEMM, f32 out)
    {
        dim3 grid(TDIM / 128, CDIM / 128, BATCH);
        gemm_fp16_cp<0><<<grid, 128, GEMM_SMEM_BYTES>>>(
            woh_p, oh_p, bout, out, nullptr, CDIM, TDIM, CDIM);
    }
}

// round 14
// speedup vs baseline: 2.1164x; 1.1547x over previous
#include <cuda_runtime.h>
#include <cuda_fp16.h>
#include <cuda_bf16.h>
#include <cstdint>

#define BATCH 4
#define CDIM  768
#define TDIM  2048
#define NHEAD 12
#define HDIM  64
#define QKVROWS (3 * CDIM)

// ---------------------------------------------------------------------------
// Device scratch (all activations fp16 now)
// ---------------------------------------------------------------------------
__device__ __half   g_qt [(size_t)BATCH * NHEAD * TDIM * HDIM]; // Q^T [b,h][t][d]
__device__ __half   g_kt [(size_t)BATCH * NHEAD * TDIM * HDIM]; // K^T [b,h][s][d]
__device__ __half   g_vh [(size_t)BATCH * CDIM * TDIM];         // V   [b][d_glob][s]
__device__ uint32_t g_oh [(size_t)BATCH * (CDIM/2) * TDIM];     // o, fp16x2 k-pair words
__device__ uint32_t g_xh [(size_t)BATCH * (CDIM/2) * TDIM];     // x, fp16x2 k-pair words
__device__ __half   g_wqh[(size_t)QKVROWS * CDIM];              // Wqkv fp16 [M][K]
__device__ __half   g_woh[(size_t)CDIM * CDIM];                 // Wout fp16 [M][K]

__device__ __forceinline__ float ex2_approx(float x) {
    float r;
    asm("ex2.approx.f32 %0, %1;" : "=f"(r) : "f"(x));
    return r;
}

// pack two f32 into fp16x2: lo -> lower half, hi -> upper half (RN)
__device__ __forceinline__ uint32_t pack_half2(float lo, float hi) {
    uint32_t r;
    asm("cvt.rn.f16x2.f32 %0, %1, %2;" : "=r"(r) : "f"(hi), "f"(lo));
    return r;
}

__device__ __forceinline__ void mma_fp16(float* c, const uint32_t* a, const uint32_t* b) {
    asm volatile(
        "mma.sync.aligned.m16n8k16.row.col.f32.f16.f16.f32 "
        "{%0,%1,%2,%3}, {%4,%5,%6,%7}, {%8,%9}, {%0,%1,%2,%3};\n"
        : "+f"(c[0]), "+f"(c[1]), "+f"(c[2]), "+f"(c[3])
        : "r"(a[0]), "r"(a[1]), "r"(a[2]), "r"(a[3]), "r"(b[0]), "r"(b[1]));
}

__device__ __forceinline__ uint32_t smem_u32(const void* p) {
    return (uint32_t)__cvta_generic_to_shared(p);
}

__device__ __forceinline__ void cp_async16(uint32_t dst, const void* src) {
    asm volatile("cp.async.cg.shared.global [%0], [%1], 16;\n"
                 :: "r"(dst), "l"(src));
}
#define CP_COMMIT() asm volatile("cp.async.commit_group;\n")

// ---------------------------------------------------------------------------
// Pack kernels
// ---------------------------------------------------------------------------
__global__ __launch_bounds__(256)
void pack_w_kernel(const float* __restrict__ in, __half* __restrict__ out, int n)
{
    int i = (blockIdx.x * 256 + threadIdx.x) * 4;
    if (i < n) {
        float4 v = *reinterpret_cast<const float4*>(in + i);
        uint2 w = make_uint2(pack_half2(v.x, v.y), pack_half2(v.z, v.w));
        *reinterpret_cast<uint2*>(out + i) = w;
    }
}

// x: f32 (B,C,T) -> fp16x2 k-pair words (B, C/2, T)
__global__ __launch_bounds__(256)
void pack_x_kernel(const float* __restrict__ x, uint32_t* __restrict__ xh)
{
    const int WPB = (CDIM / 2) * (TDIM / 4);
    int idx = blockIdx.x * 256 + threadIdx.x;
    int b   = idx / WPB;
    int r   = idx % WPB;
    int kp  = r / (TDIM / 4);
    int t4  = (r % (TDIM / 4)) * 4;
    const float* r0 = x + ((size_t)b * CDIM + 2 * kp) * TDIM + t4;
    float4 a = *reinterpret_cast<const float4*>(r0);
    float4 c = *reinterpret_cast<const float4*>(r0 + TDIM);
    uint4 w = make_uint4(pack_half2(a.x, c.x), pack_half2(a.y, c.y),
                         pack_half2(a.z, c.z), pack_half2(a.w, c.w));
    *reinterpret_cast<uint4*>(xh + ((size_t)b * (CDIM / 2) + kp) * TDIM + t4) = w;
}

// ---------------------------------------------------------------------------
// fp16 GEMM (f32 accum): 128x128 tile, 128 thr (2x2 warps, 64x64 warp tile),
// kTile=32 (2 x k16 steps), cp.async double buffered.
// MODE 0: C = f32 + bias.
// MODE 1 (qkv): Q rows -> qT fp16 [t][d]; K rows -> kT fp16 [s][d];
//               V rows -> vh fp16 [d][s]. No f32 output.
// ---------------------------------------------------------------------------
#define GA_WW (128 * 20)
#define GB_WW (16 * 136)
#define GEMM_SMEM_BYTES ((2 * GA_WW + 2 * GB_WW) * 4)

template<int MODE>
__global__ __launch_bounds__(128, 2)
void gemm_fp16_cp(const __half* __restrict__ Ah,
                  const uint32_t* __restrict__ Bw,
                  const float* __restrict__ bias,
                  float* __restrict__ Cmat,
                  __half* __restrict__ qroot,
                  __half* __restrict__ kroot,
                  __half* __restrict__ vroot,
                  int M, int N, int K)
{
    extern __shared__ uint32_t gsm[];

    const uint32_t* Bp = Bw + (size_t)blockIdx.z * (size_t)(K / 2) * N;
    float*          Cp = (MODE == 0) ? Cmat + (size_t)blockIdx.z * (size_t)M * N : nullptr;

    const int tid  = threadIdx.x;
    const int lane = tid & 31;
    const int warp = tid >> 5;
    const int g    = lane >> 2;
    const int tig  = lane & 3;
    const int wm   = warp >> 1;
    const int wn   = warp & 1;
    const int row0 = blockIdx.y * 128;
    const int col0 = blockIdx.x * 128;

    const uint32_t sbase = smem_u32(gsm);

    float acc[4][8][4];
    #pragma unroll
    for (int i = 0; i < 4; i++)
        #pragma unroll
        for (int j = 0; j < 8; j++)
            #pragma unroll
            for (int r = 0; r < 4; r++) acc[i][j][r] = 0.0f;

    const int KT = K >> 5;

    auto issue = [&](int s) {
        const int k0 = s * 32;
        const uint32_t abase = sbase + (unsigned)((s & 1) * GA_WW) * 4u;
        const uint32_t bbase = sbase + (unsigned)(2 * GA_WW + (s & 1) * GB_WW) * 4u;
        #pragma unroll
        for (int l = 0; l < 4; l++) {
            int lin = tid + l * 128;
            int m   = lin >> 2;
            int kw4 = (lin & 3) * 4;
            cp_async16(abase + (unsigned)(m * 20 + kw4) * 4u,
                       Ah + (size_t)(row0 + m) * K + k0 + kw4 * 2);
        }
        #pragma unroll
        for (int l = 0; l < 4; l++) {
            int lin = tid + l * 128;
            int kw  = lin >> 5;
            int n4  = (lin & 31) * 4;
            cp_async16(bbase + (unsigned)(kw * 136 + n4) * 4u,
                       Bp + (size_t)(k0 / 2 + kw) * N + col0 + n4);
        }
        CP_COMMIT();
    };

    issue(0);
    if (KT > 1) issue(1);

    for (int kt = 0; kt < KT; kt++) {
        const int buf = kt & 1;
        if (kt + 1 < KT) asm volatile("cp.async.wait_group 1;\n");
        else             asm volatile("cp.async.wait_group 0;\n");
        __syncthreads();

        const uint32_t* Ab = gsm + buf * GA_WW;
        const uint32_t* Bb = gsm + 2 * GA_WW + buf * GB_WW;

        #pragma unroll
        for (int ks = 0; ks < 2; ks++) {
            const int kwb = ks * 8;
            uint32_t af[4][4];
            uint32_t bf[8][2];
            #pragma unroll
            for (int mi = 0; mi < 4; mi++) {
                int m = wm * 64 + mi * 16 + g;
                af[mi][0] = Ab[m * 20 + kwb + tig];
                af[mi][1] = Ab[(m + 8) * 20 + kwb + tig];
                af[mi][2] = Ab[m * 20 + kwb + tig + 4];
                af[mi][3] = Ab[(m + 8) * 20 + kwb + tig + 4];
            }
            #pragma unroll
            for (int ni = 0; ni < 8; ni++) {
                int n = wn * 64 + ni * 8 + g;
                bf[ni][0] = Bb[(kwb + tig) * 136 + n];
                bf[ni][1] = Bb[(kwb + tig + 4) * 136 + n];
            }
            #pragma unroll
            for (int mi = 0; mi < 4; mi++)
                #pragma unroll
                for (int ni = 0; ni < 8; ni++)
                    mma_fp16(acc[mi][ni], af[mi], bf[ni]);
        }

        __syncthreads();
        if (kt + 2 < KT) issue(kt + 2);
    }

    #pragma unroll
    for (int mi = 0; mi < 4; mi++) {
        int r0 = row0 + wm * 64 + mi * 16 + g;
        float b0 = bias[r0];
        float b1 = bias[r0 + 8];
        if (MODE == 0) {
            #pragma unroll
            for (int ni = 0; ni < 8; ni++) {
                int cc = col0 + wn * 64 + ni * 8 + tig * 2;
                *reinterpret_cast<float2*>(Cp + (size_t)r0 * N + cc) =
                    make_float2(acc[mi][ni][0] + b0, acc[mi][ni][1] + b0);
                *reinterpret_cast<float2*>(Cp + (size_t)(r0 + 8) * N + cc) =
                    make_float2(acc[mi][ni][2] + b1, acc[mi][ni][3] + b1);
            }
        } else {
            const int cls  = r0 / CDIM;              // 0=Q, 1=K, 2=V (uniform per warp row-block)
            if (cls == 2) {
                __half* Vp = vroot + (size_t)blockIdx.z * CDIM * TDIM;
                #pragma unroll
                for (int ni = 0; ni < 8; ni++) {
                    int cc = col0 + wn * 64 + ni * 8 + tig * 2;
                    __half* vp = Vp + (size_t)(r0 - 2 * CDIM) * N + cc;
                    *reinterpret_cast<uint32_t*>(vp) =
                        pack_half2(acc[mi][ni][0] + b0, acc[mi][ni][1] + b0);
                    *reinterpret_cast<uint32_t*>(vp + (size_t)8 * N) =
                        pack_half2(acc[mi][ni][2] + b1, acc[mi][ni][3] + b1);
                }
            } else {
                const int head = (r0 % CDIM) / HDIM;
                const int d    = r0 % HDIM;          // d and d+8 same head
                __half* tb = (cls == 0 ? qroot : kroot)
                           + ((size_t)(blockIdx.z * NHEAD + head) * TDIM) * HDIM;
                #pragma unroll
                for (int ni = 0; ni < 8; ni++) {
                    int cc = col0 + wn * 64 + ni * 8 + tig * 2;
                    __half* p0 = tb + (size_t)cc * HDIM + d;
                    __half* p1 = tb + (size_t)(cc + 1) * HDIM + d;
                    p0[0] = __float2half_rn(acc[mi][ni][0] + b0);
                    p1[0] = __float2half_rn(acc[mi][ni][1] + b0);
                    p0[8] = __float2half_rn(acc[mi][ni][2] + b1);
                    p1[8] = __float2half_rn(acc[mi][ni][3] + b1);
                }
            }
        }
    }
}

// ---------------------------------------------------------------------------
// Flash attention v11: all-fp16 MMA (f32 accum).
//  - S = Q K^T in fp16 k16: Q^T [t][d] frags from gmem (32 regs),
//    K staged [s][d/2 words] pitch 36 -> frag pattern mirrors validated PV
//  - P packed fp16x2 after exp (zero-shuffle relayout), PV fp16 k16
//  - 3-stage cp.async ring, ex2 softmax, epilogue writes packed fp16 o
// grid (T/256, H, B), 256 threads, warp tile 32t x 64s / 32t x 64d.
// ---------------------------------------------------------------------------
#define KW_P 36
#define VW_P 36
#define FA_TBLK 256
#define KSTG (64 * KW_P)
#define VSTG (64 * VW_P)
#define FA_NCHUNK (TDIM / 64)
#define FA_SMEM_WORDS (3 * KSTG + 3 * VSTG + TDIM)
#define FA_SMEM_BYTES (FA_SMEM_WORDS * 4)
#define LOG2E 1.44269504088896340736f

__global__ __launch_bounds__(256, 1)
void flash_attn_v11(const int* __restrict__ mask)
{
    extern __shared__ uint32_t fsm[];
    uint32_t* Ks      = fsm;                       // 3 stages [s][d/2] fp16x2, pitch 36
    uint32_t* Vs      = Ks + 3 * KSTG;             // 3 stages [d][s/2] fp16x2, pitch 36
    float*    maskAll = (float*)(Vs + 3 * VSTG);   // 2048 biases (pre-scaled by log2e)

    const int b    = blockIdx.z;
    const int h    = blockIdx.y;
    const int tt   = blockIdx.x;
    const int tid  = threadIdx.x;
    const int lane = tid & 31;
    const int warp = tid >> 5;
    const int g    = lane >> 2;
    const int tig  = lane & 3;
    const int tw   = warp * 32;

    const __half* qptr = g_qt + ((size_t)(b * NHEAD + h) * TDIM + tt * FA_TBLK + tw) * HDIM;
    const __half* kptr = g_kt + ((size_t)(b * NHEAD + h) * TDIM) * HDIM;
    const __half* vptr = g_vh + (size_t)b * CDIM * TDIM + (size_t)(h * HDIM) * TDIM;

    const uint32_t kbase0 = smem_u32(Ks);
    const uint32_t vbase0 = smem_u32(Vs);

    auto issue = [&](int ch) {
        const uint32_t kb = kbase0 + (unsigned)((ch % 3) * KSTG) * 4u;
        const uint32_t vb = vbase0 + (unsigned)((ch % 3) * VSTG) * 4u;
        const int s0 = ch * 64;
        #pragma unroll
        for (int l = 0; l < 2; l++) {          // K: 64 s rows x 8 segs of 16B
            int lin = tid + l * 256;
            int s   = lin >> 3;
            int seg = lin & 7;
            cp_async16(kb + (unsigned)(s * KW_P * 4 + seg * 16),
                       kptr + (size_t)(s0 + s) * HDIM + seg * 8);
        }
        #pragma unroll
        for (int l = 0; l < 2; l++) {          // V: 64 d rows x 8 segs of 16B
            int lin = tid + l * 256;
            int d   = lin >> 3;
            int seg = lin & 7;
            cp_async16(vb + (unsigned)(d * VW_P * 4 + seg * 16),
                       vptr + (size_t)d * TDIM + s0 + seg * 8);
        }
        CP_COMMIT();
    };

    issue(0); issue(1); issue(2);

    // Q fragments (fp16 d-pair words) from gmem, once per block.
    // a0=(t, k=2tig..), a1=(t+8), a2=(t, k=8+2tig), a3=(t+8, k=8+2tig)
    uint32_t Qf[2][4][4];
    #pragma unroll
    for (int mi = 0; mi < 2; mi++) {
        const __half* qrow0 = qptr + (size_t)(mi * 16 + g) * HDIM;
        const __half* qrow1 = qrow0 + (size_t)8 * HDIM;
        #pragma unroll
        for (int kk = 0; kk < 4; kk++) {
            Qf[mi][kk][0] = *reinterpret_cast<const uint32_t*>(qrow0 + (kk * 8 + tig) * 2);
            Qf[mi][kk][1] = *reinterpret_cast<const uint32_t*>(qrow1 + (kk * 8 + tig) * 2);
            Qf[mi][kk][2] = *reinterpret_cast<const uint32_t*>(qrow0 + (kk * 8 + tig + 4) * 2);
            Qf[mi][kk][3] = *reinterpret_cast<const uint32_t*>(qrow1 + (kk * 8 + tig + 4) * 2);
        }
    }

    for (int i = tid; i < TDIM; i += 256)
        maskAll[i] = (mask[(size_t)b * TDIM + i] == 0) ? (-10000.0f * LOG2E) : 0.0f;

    float accO[2][8][4];
    #pragma unroll
    for (int mi = 0; mi < 2; mi++)
        #pragma unroll
        for (int ni = 0; ni < 8; ni++)
            #pragma unroll
            for (int r = 0; r < 4; r++) accO[mi][ni][r] = 0.0f;

    float rowl[2][2] = {{0.0f, 0.0f}, {0.0f, 0.0f}};

    const float sc2 = 0.125f * LOG2E;

    for (int kt = 0; kt < FA_NCHUNK; kt++) {
        if      (kt + 2 < FA_NCHUNK) asm volatile("cp.async.wait_group 2;\n");
        else if (kt + 1 < FA_NCHUNK) asm volatile("cp.async.wait_group 1;\n");
        else                         asm volatile("cp.async.wait_group 0;\n");
        __syncthreads();

        const uint32_t* Kw = Ks + (kt % 3) * KSTG;
        const uint32_t* Vw = Vs + (kt % 3) * VSTG;
        const float*    mb = maskAll + kt * 64;

        // ---- S = Q K^T (fp16 k16), 4 k-steps over d=64 ----
        float sacc[2][8][4];
        #pragma unroll
        for (int mi = 0; mi < 2; mi++)
            #pragma unroll
            for (int ni = 0; ni < 8; ni++)
                #pragma unroll
                for (int r = 0; r < 4; r++) sacc[mi][ni][r] = 0.0f;

        #pragma unroll
        for (int kk = 0; kk < 4; kk++) {
            uint32_t bf[8][2];
            #pragma unroll
            for (int ni = 0; ni < 8; ni++) {
                bf[ni][0] = Kw[(ni * 8 + g) * KW_P + kk * 8 + tig];
                bf[ni][1] = Kw[(ni * 8 + g) * KW_P + kk * 8 + 4 + tig];
            }
            #pragma unroll
            for (int mi = 0; mi < 2; mi++)
                #pragma unroll
                for (int ni = 0; ni < 8; ni++)
                    mma_fp16(sacc[mi][ni], Qf[mi][kk], bf[ni]);
        }

        // ---- softmax numerators, pack P to fp16x2 (s-pairs) ----
        uint32_t pp[2][8][2];
        float rs[2][2] = {{0.0f, 0.0f}, {0.0f, 0.0f}};
        #pragma unroll
        for (int mi = 0; mi < 2; mi++)
            #pragma unroll
            for (int ni = 0; ni < 8; ni++) {
                int sb = ni * 8 + tig * 2;
                float b0 = mb[sb], b1 = mb[sb + 1];
                float p0 = ex2_approx(fmaf(sacc[mi][ni][0], sc2, b0));
                float p1 = ex2_approx(fmaf(sacc[mi][ni][1], sc2, b1));
                float p2 = ex2_approx(fmaf(sacc[mi][ni][2], sc2, b0));
                float p3 = ex2_approx(fmaf(sacc[mi][ni][3], sc2, b1));
                rs[mi][0] += p0 + p1;
                rs[mi][1] += p2 + p3;
                pp[mi][ni][0] = pack_half2(p0, p1);
                pp[mi][ni][1] = pack_half2(p2, p3);
            }
        #pragma unroll
        for (int mi = 0; mi < 2; mi++)
            #pragma unroll
            for (int j = 0; j < 2; j++) {
                float r = rs[mi][j];
                r += __shfl_xor_sync(0xffffffffu, r, 1);
                r += __shfl_xor_sync(0xffffffffu, r, 2);
                rowl[mi][j] += r;
            }

        // ---- O += P V (fp16 k16), 4 k-blocks of 16 s ----
        #pragma unroll
        for (int kb = 0; kb < 4; kb++) {
            uint32_t bf[8][2];
            #pragma unroll
            for (int ni = 0; ni < 8; ni++) {
                bf[ni][0] = Vw[(ni * 8 + g) * VW_P + kb * 8 + tig];
                bf[ni][1] = Vw[(ni * 8 + g) * VW_P + kb * 8 + 4 + tig];
            }
            #pragma unroll
            for (int mi = 0; mi < 2; mi++) {
                uint32_t a[4] = { pp[mi][2 * kb][0],     pp[mi][2 * kb][1],
                                  pp[mi][2 * kb + 1][0], pp[mi][2 * kb + 1][1] };
                #pragma unroll
                for (int ni = 0; ni < 8; ni++)
                    mma_fp16(accO[mi][ni], a, bf[ni]);
            }
        }

        __syncthreads();
        if (kt + 3 < FA_NCHUNK) issue(kt + 3);
    }

    // ---- epilogue: normalize, write o as fp16x2 k-pair words ----
    uint32_t* ohp = g_oh + (size_t)b * (CDIM / 2) * TDIM
                  + (size_t)(h * (HDIM / 2)) * TDIM + tt * FA_TBLK + tw;
    #pragma unroll
    for (int mi = 0; mi < 2; mi++) {
        float il0 = 1.0f / rowl[mi][0];
        float il1 = 1.0f / rowl[mi][1];
        #pragma unroll
        for (int ni = 0; ni < 8; ni++) {
            int dw = ni * 4 + tig;
            uint32_t* op = ohp + (size_t)dw * TDIM + mi * 16 + g;
            op[0] = pack_half2(accO[mi][ni][0] * il0, accO[mi][ni][1] * il0);
            op[8] = pack_half2(accO[mi][ni][2] * il1, accO[mi][ni][3] * il1);
        }
    }
}

// ---------------------------------------------------------------------------
// kernel_launch (single stream, graph-safe)
// ---------------------------------------------------------------------------
extern "C" void kernel_launch(void* const* d_in, const int* in_sizes, int n_in,
                              void* d_out, int out_size)
{
    const float* x    = (const float*)d_in[0];
    const int*   mask = (const int*)  d_in[1];
    const float* Wqkv = (const float*)d_in[2];
    const float* bqkv = (const float*)d_in[3];
    const float* Wout = (const float*)d_in[4];
    const float* bout = (const float*)d_in[5];
    float*       out  = (float*)d_out;

    __half *qt_p, *kt_p, *vh_p, *wqh_p, *woh_p;
    uint32_t *oh_p, *xh_p;
    cudaGetSymbolAddress((void**)&qt_p,  g_qt);
    cudaGetSymbolAddress((void**)&kt_p,  g_kt);
    cudaGetSymbolAddress((void**)&vh_p,  g_vh);
    cudaGetSymbolAddress((void**)&oh_p,  g_oh);
    cudaGetSymbolAddress((void**)&xh_p,  g_xh);
    cudaGetSymbolAddress((void**)&wqh_p, g_wqh);
    cudaGetSymbolAddress((void**)&woh_p, g_woh);

    cudaFuncSetAttribute(gemm_fp16_cp<0>,
                         cudaFuncAttributeMaxDynamicSharedMemorySize, GEMM_SMEM_BYTES);
    cudaFuncSetAttribute(gemm_fp16_cp<1>,
                         cudaFuncAttributeMaxDynamicSharedMemorySize, GEMM_SMEM_BYTES);
    cudaFuncSetAttribute(flash_attn_v11,
                         cudaFuncAttributeMaxDynamicSharedMemorySize, FA_SMEM_BYTES);

    // 0) pack inputs to fp16
    {
        const int nq = QKVROWS * CDIM;
        const int nw = CDIM * CDIM;
        const int nxw4 = BATCH * (CDIM / 2) * (TDIM / 4);
        pack_w_kernel<<<nq / 1024, 256>>>(Wqkv, wqh_p, nq);
        pack_w_kernel<<<nw / 1024, 256>>>(Wout, woh_p, nw);
        pack_x_kernel<<<nxw4 / 256, 256>>>(x, xh_p);
    }

    // 1) qkv = Wqkv @ x + bqkv  (Q -> qT, K -> kT, V -> vh, all fp16)
    {
        dim3 grid(TDIM / 128, QKVROWS / 128, BATCH);
        gemm_fp16_cp<1><<<grid, 128, GEMM_SMEM_BYTES>>>(
            wqh_p, xh_p, bqkv, nullptr, qt_p, kt_p, vh_p, QKVROWS, TDIM, CDIM);
    }
    // 2) fused flash attention (all-fp16 MMA, f32 accum)
    {
        dim3 grid(TDIM / FA_TBLK, NHEAD, BATCH);
        flash_attn_v11<<<grid, 256, FA_SMEM_BYTES>>>(mask);
    }
    // 3) out = Wout @ o + bout  (fp16 GEMM, f32 out)
    {
        dim3 grid(TDIM / 128, CDIM / 128, BATCH);
        gemm_fp16_cp<0><<<grid, 128, GEMM_SMEM_BYTES>>>(
            woh_p, oh_p, bout, out, nullptr, nullptr, nullptr, CDIM, TDIM, CDIM);
    }
}

// round 15
// speedup vs baseline: 2.2450x; 1.0608x over previous
#include <cuda_runtime.h>
#include <cuda_fp16.h>
#include <cuda_bf16.h>
#include <cstdint>

#define BATCH 4
#define CDIM  768
#define TDIM  2048
#define NHEAD 12
#define HDIM  64
#define QKVROWS (3 * CDIM)

// ---------------------------------------------------------------------------
// Device scratch (all activations fp16)
// ---------------------------------------------------------------------------
__device__ __half   g_qt [(size_t)BATCH * NHEAD * TDIM * HDIM]; // Q^T [b,h][t][d]
__device__ __half   g_kt [(size_t)BATCH * NHEAD * TDIM * HDIM]; // K^T [b,h][s][d]
__device__ __half   g_vh [(size_t)BATCH * CDIM * TDIM];         // V   [b][d_glob][s]
__device__ uint32_t g_oh [(size_t)BATCH * (CDIM/2) * TDIM];     // o, fp16x2 k-pair words
__device__ uint32_t g_xh [(size_t)BATCH * (CDIM/2) * TDIM];     // x, fp16x2 k-pair words
__device__ __half   g_wqh[(size_t)QKVROWS * CDIM];              // Wqkv fp16 [M][K]
__device__ __half   g_woh[(size_t)CDIM * CDIM];                 // Wout fp16 [M][K]

// pack two f32 into fp16x2: lo -> lower half, hi -> upper half (RN)
__device__ __forceinline__ uint32_t pack_half2(float lo, float hi) {
    uint32_t r;
    asm("cvt.rn.f16x2.f32 %0, %1, %2;" : "=r"(r) : "f"(hi), "f"(lo));
    return r;
}

// p2 = ex2.approx.f16x2( s2 * sc2 + b2 )   (all fp16x2)
__device__ __forceinline__ uint32_t h2_fma_ex2(uint32_t s2, uint32_t sc2x2, uint32_t b2) {
    uint32_t r;
    asm("{ .reg .b32 t;\n"
        "  fma.rn.f16x2 t, %1, %2, %3;\n"
        "  ex2.approx.f16x2 %0, t; }\n"
        : "=r"(r) : "r"(s2), "r"(sc2x2), "r"(b2));
    return r;
}

__device__ __forceinline__ void mma_fp16(float* c, const uint32_t* a, const uint32_t* b) {
    asm volatile(
        "mma.sync.aligned.m16n8k16.row.col.f32.f16.f16.f32 "
        "{%0,%1,%2,%3}, {%4,%5,%6,%7}, {%8,%9}, {%0,%1,%2,%3};\n"
        : "+f"(c[0]), "+f"(c[1]), "+f"(c[2]), "+f"(c[3])
        : "r"(a[0]), "r"(a[1]), "r"(a[2]), "r"(a[3]), "r"(b[0]), "r"(b[1]));
}

__device__ __forceinline__ uint32_t smem_u32(const void* p) {
    return (uint32_t)__cvta_generic_to_shared(p);
}

__device__ __forceinline__ void cp_async16(uint32_t dst, const void* src) {
    asm volatile("cp.async.cg.shared.global [%0], [%1], 16;\n"
                 :: "r"(dst), "l"(src));
}
#define CP_COMMIT() asm volatile("cp.async.commit_group;\n")

// ---------------------------------------------------------------------------
// Pack kernels
// ---------------------------------------------------------------------------
__global__ __launch_bounds__(256)
void pack_w_kernel(const float* __restrict__ in, __half* __restrict__ out, int n)
{
    int i = (blockIdx.x * 256 + threadIdx.x) * 4;
    if (i < n) {
        float4 v = *reinterpret_cast<const float4*>(in + i);
        uint2 w = make_uint2(pack_half2(v.x, v.y), pack_half2(v.z, v.w));
        *reinterpret_cast<uint2*>(out + i) = w;
    }
}

// x: f32 (B,C,T) -> fp16x2 k-pair words (B, C/2, T)
__global__ __launch_bounds__(256)
void pack_x_kernel(const float* __restrict__ x, uint32_t* __restrict__ xh)
{
    const int WPB = (CDIM / 2) * (TDIM / 4);
    int idx = blockIdx.x * 256 + threadIdx.x;
    int b   = idx / WPB;
    int r   = idx % WPB;
    int kp  = r / (TDIM / 4);
    int t4  = (r % (TDIM / 4)) * 4;
    const float* r0 = x + ((size_t)b * CDIM + 2 * kp) * TDIM + t4;
    float4 a = *reinterpret_cast<const float4*>(r0);
    float4 c = *reinterpret_cast<const float4*>(r0 + TDIM);
    uint4 w = make_uint4(pack_half2(a.x, c.x), pack_half2(a.y, c.y),
                         pack_half2(a.z, c.z), pack_half2(a.w, c.w));
    *reinterpret_cast<uint4*>(xh + ((size_t)b * (CDIM / 2) + kp) * TDIM + t4) = w;
}

// ---------------------------------------------------------------------------
// fp16 GEMM (f32 accum): identical to R14.
// ---------------------------------------------------------------------------
#define GA_WW (128 * 20)
#define GB_WW (16 * 136)
#define GEMM_SMEM_BYTES ((2 * GA_WW + 2 * GB_WW) * 4)

template<int MODE>
__global__ __launch_bounds__(128, 2)
void gemm_fp16_cp(const __half* __restrict__ Ah,
                  const uint32_t* __restrict__ Bw,
                  const float* __restrict__ bias,
                  float* __restrict__ Cmat,
                  __half* __restrict__ qroot,
                  __half* __restrict__ kroot,
                  __half* __restrict__ vroot,
                  int M, int N, int K)
{
    extern __shared__ uint32_t gsm[];

    const uint32_t* Bp = Bw + (size_t)blockIdx.z * (size_t)(K / 2) * N;
    float*          Cp = (MODE == 0) ? Cmat + (size_t)blockIdx.z * (size_t)M * N : nullptr;

    const int tid  = threadIdx.x;
    const int lane = tid & 31;
    const int warp = tid >> 5;
    const int g    = lane >> 2;
    const int tig  = lane & 3;
    const int wm   = warp >> 1;
    const int wn   = warp & 1;
    const int row0 = blockIdx.y * 128;
    const int col0 = blockIdx.x * 128;

    const uint32_t sbase = smem_u32(gsm);

    float acc[4][8][4];
    #pragma unroll
    for (int i = 0; i < 4; i++)
        #pragma unroll
        for (int j = 0; j < 8; j++)
            #pragma unroll
            for (int r = 0; r < 4; r++) acc[i][j][r] = 0.0f;

    const int KT = K >> 5;

    auto issue = [&](int s) {
        const int k0 = s * 32;
        const uint32_t abase = sbase + (unsigned)((s & 1) * GA_WW) * 4u;
        const uint32_t bbase = sbase + (unsigned)(2 * GA_WW + (s & 1) * GB_WW) * 4u;
        #pragma unroll
        for (int l = 0; l < 4; l++) {
            int lin = tid + l * 128;
            int m   = lin >> 2;
            int kw4 = (lin & 3) * 4;
            cp_async16(abase + (unsigned)(m * 20 + kw4) * 4u,
                       Ah + (size_t)(row0 + m) * K + k0 + kw4 * 2);
        }
        #pragma unroll
        for (int l = 0; l < 4; l++) {
            int lin = tid + l * 128;
            int kw  = lin >> 5;
            int n4  = (lin & 31) * 4;
            cp_async16(bbase + (unsigned)(kw * 136 + n4) * 4u,
                       Bp + (size_t)(k0 / 2 + kw) * N + col0 + n4);
        }
        CP_COMMIT();
    };

    issue(0);
    if (KT > 1) issue(1);

    for (int kt = 0; kt < KT; kt++) {
        const int buf = kt & 1;
        if (kt + 1 < KT) asm volatile("cp.async.wait_group 1;\n");
        else             asm volatile("cp.async.wait_group 0;\n");
        __syncthreads();

        const uint32_t* Ab = gsm + buf * GA_WW;
        const uint32_t* Bb = gsm + 2 * GA_WW + buf * GB_WW;

        #pragma unroll
        for (int ks = 0; ks < 2; ks++) {
            const int kwb = ks * 8;
            uint32_t af[4][4];
            uint32_t bf[8][2];
            #pragma unroll
            for (int mi = 0; mi < 4; mi++) {
                int m = wm * 64 + mi * 16 + g;
                af[mi][0] = Ab[m * 20 + kwb + tig];
                af[mi][1] = Ab[(m + 8) * 20 + kwb + tig];
                af[mi][2] = Ab[m * 20 + kwb + tig + 4];
                af[mi][3] = Ab[(m + 8) * 20 + kwb + tig + 4];
            }
            #pragma unroll
            for (int ni = 0; ni < 8; ni++) {
                int n = wn * 64 + ni * 8 + g;
                bf[ni][0] = Bb[(kwb + tig) * 136 + n];
                bf[ni][1] = Bb[(kwb + tig + 4) * 136 + n];
            }
            #pragma unroll
            for (int mi = 0; mi < 4; mi++)
                #pragma unroll
                for (int ni = 0; ni < 8; ni++)
                    mma_fp16(acc[mi][ni], af[mi], bf[ni]);
        }

        __syncthreads();
        if (kt + 2 < KT) issue(kt + 2);
    }

    #pragma unroll
    for (int mi = 0; mi < 4; mi++) {
        int r0 = row0 + wm * 64 + mi * 16 + g;
        float b0 = bias[r0];
        float b1 = bias[r0 + 8];
        if (MODE == 0) {
            #pragma unroll
            for (int ni = 0; ni < 8; ni++) {
                int cc = col0 + wn * 64 + ni * 8 + tig * 2;
                *reinterpret_cast<float2*>(Cp + (size_t)r0 * N + cc) =
                    make_float2(acc[mi][ni][0] + b0, acc[mi][ni][1] + b0);
                *reinterpret_cast<float2*>(Cp + (size_t)(r0 + 8) * N + cc) =
                    make_float2(acc[mi][ni][2] + b1, acc[mi][ni][3] + b1);
            }
        } else {
            const int cls  = r0 / CDIM;              // 0=Q, 1=K, 2=V
            if (cls == 2) {
                __half* Vp = vroot + (size_t)blockIdx.z * CDIM * TDIM;
                #pragma unroll
                for (int ni = 0; ni < 8; ni++) {
                    int cc = col0 + wn * 64 + ni * 8 + tig * 2;
                    __half* vp = Vp + (size_t)(r0 - 2 * CDIM) * N + cc;
                    *reinterpret_cast<uint32_t*>(vp) =
                        pack_half2(acc[mi][ni][0] + b0, acc[mi][ni][1] + b0);
                    *reinterpret_cast<uint32_t*>(vp + (size_t)8 * N) =
                        pack_half2(acc[mi][ni][2] + b1, acc[mi][ni][3] + b1);
                }
            } else {
                const int head = (r0 % CDIM) / HDIM;
                const int d    = r0 % HDIM;
                __half* tb = (cls == 0 ? qroot : kroot)
                           + ((size_t)(blockIdx.z * NHEAD + head) * TDIM) * HDIM;
                #pragma unroll
                for (int ni = 0; ni < 8; ni++) {
                    int cc = col0 + wn * 64 + ni * 8 + tig * 2;
                    __half* p0 = tb + (size_t)cc * HDIM + d;
                    __half* p1 = tb + (size_t)(cc + 1) * HDIM + d;
                    p0[0] = __float2half_rn(acc[mi][ni][0] + b0);
                    p1[0] = __float2half_rn(acc[mi][ni][1] + b0);
                    p0[8] = __float2half_rn(acc[mi][ni][2] + b1);
                    p1[8] = __float2half_rn(acc[mi][ni][3] + b1);
                }
            }
        }
    }
}

// ---------------------------------------------------------------------------
// Flash attention v12: all-fp16 MMA + f16x2 softmax + tensor-core row sums.
//  - S = Q K^T fp16 k16 (Q^T frags from gmem)
//  - softmax: pack s-pairs to half2, one HFMA2 (scale + half2 mask bias),
//    one ex2.approx.f16x2 -> pp directly (MUFU halved, no f32 FMAs, no packs)
//  - row sums: extra MMA with B = ones into persistent accS (f32 C-frags);
//    columns duplicated -> epilogue reads rowl with no shuffles
//  - PV fp16 k16, 3-stage cp.async ring
// grid (T/256, H, B), 256 threads, warp tile 32t x 64s / 32t x 64d.
// ---------------------------------------------------------------------------
#define KW_P 36
#define VW_P 36
#define FA_TBLK 256
#define KSTG (64 * KW_P)
#define VSTG (64 * VW_P)
#define FA_NCHUNK (TDIM / 64)
#define FA_SMEM_WORDS (3 * KSTG + 3 * VSTG + TDIM / 2)
#define FA_SMEM_BYTES (FA_SMEM_WORDS * 4)
#define LOG2E 1.44269504088896340736f
#define ONES_H2 0x3C003C00u

__global__ __launch_bounds__(256, 1)
void flash_attn_v12(const int* __restrict__ mask)
{
    extern __shared__ uint32_t fsm[];
    uint32_t* Ks    = fsm;                     // 3 stages [s][d/2] fp16x2, pitch 36
    uint32_t* Vs    = Ks + 3 * KSTG;           // 3 stages [d][s/2] fp16x2, pitch 36
    uint32_t* maskW = Vs + 3 * VSTG;           // 1024 half2 bias words (pre-scaled)

    const int b    = blockIdx.z;
    const int h    = blockIdx.y;
    const int tt   = blockIdx.x;
    const int tid  = threadIdx.x;
    const int lane = tid & 31;
    const int warp = tid >> 5;
    const int g    = lane >> 2;
    const int tig  = lane & 3;
    const int tw   = warp * 32;

    const __half* qptr = g_qt + ((size_t)(b * NHEAD + h) * TDIM + tt * FA_TBLK + tw) * HDIM;
    const __half* kptr = g_kt + ((size_t)(b * NHEAD + h) * TDIM) * HDIM;
    const __half* vptr = g_vh + (size_t)b * CDIM * TDIM + (size_t)(h * HDIM) * TDIM;

    const uint32_t kbase0 = smem_u32(Ks);
    const uint32_t vbase0 = smem_u32(Vs);

    auto issue = [&](int ch) {
        const uint32_t kb = kbase0 + (unsigned)((ch % 3) * KSTG) * 4u;
        const uint32_t vb = vbase0 + (unsigned)((ch % 3) * VSTG) * 4u;
        const int s0 = ch * 64;
        #pragma unroll
        for (int l = 0; l < 2; l++) {
            int lin = tid + l * 256;
            int s   = lin >> 3;
            int seg = lin & 7;
            cp_async16(kb + (unsigned)(s * KW_P * 4 + seg * 16),
                       kptr + (size_t)(s0 + s) * HDIM + seg * 8);
        }
        #pragma unroll
        for (int l = 0; l < 2; l++) {
            int lin = tid + l * 256;
            int d   = lin >> 3;
            int seg = lin & 7;
            cp_async16(vb + (unsigned)(d * VW_P * 4 + seg * 16),
                       vptr + (size_t)d * TDIM + s0 + seg * 8);
        }
        CP_COMMIT();
    };

    issue(0); issue(1); issue(2);

    // Q fragments (fp16 d-pair words), once per block.
    uint32_t Qf[2][4][4];
    #pragma unroll
    for (int mi = 0; mi < 2; mi++) {
        const __half* qrow0 = qptr + (size_t)(mi * 16 + g) * HDIM;
        const __half* qrow1 = qrow0 + (size_t)8 * HDIM;
        #pragma unroll
        for (int kk = 0; kk < 4; kk++) {
            Qf[mi][kk][0] = *reinterpret_cast<const uint32_t*>(qrow0 + (kk * 8 + tig) * 2);
            Qf[mi][kk][1] = *reinterpret_cast<const uint32_t*>(qrow1 + (kk * 8 + tig) * 2);
            Qf[mi][kk][2] = *reinterpret_cast<const uint32_t*>(qrow0 + (kk * 8 + tig + 4) * 2);
            Qf[mi][kk][3] = *reinterpret_cast<const uint32_t*>(qrow1 + (kk * 8 + tig + 4) * 2);
        }
    }

    // mask biases as half2 words, pre-scaled by log2(e)
    for (int i = tid; i < TDIM / 2; i += 256) {
        float b0 = (mask[(size_t)b * TDIM + 2 * i]     == 0) ? (-10000.0f * LOG2E) : 0.0f;
        float b1 = (mask[(size_t)b * TDIM + 2 * i + 1] == 0) ? (-10000.0f * LOG2E) : 0.0f;
        maskW[i] = pack_half2(b0, b1);
    }

    float accO[2][8][4];
    #pragma unroll
    for (int mi = 0; mi < 2; mi++)
        #pragma unroll
        for (int ni = 0; ni < 8; ni++)
            #pragma unroll
            for (int r = 0; r < 4; r++) accO[mi][ni][r] = 0.0f;

    float accS[2][4];    // persistent row-sum C-frags (cols duplicated)
    #pragma unroll
    for (int mi = 0; mi < 2; mi++)
        #pragma unroll
        for (int r = 0; r < 4; r++) accS[mi][r] = 0.0f;

    const float sc2f = 0.125f * LOG2E;
    const uint32_t sc2x2 = pack_half2(sc2f, sc2f);
    const uint32_t onesb[2] = { ONES_H2, ONES_H2 };

    for (int kt = 0; kt < FA_NCHUNK; kt++) {
        if      (kt + 2 < FA_NCHUNK) asm volatile("cp.async.wait_group 2;\n");
        else if (kt + 1 < FA_NCHUNK) asm volatile("cp.async.wait_group 1;\n");
        else                         asm volatile("cp.async.wait_group 0;\n");
        __syncthreads();

        const uint32_t* Kw = Ks + (kt % 3) * KSTG;
        const uint32_t* Vw = Vs + (kt % 3) * VSTG;
        const uint32_t* mw = maskW + kt * 32;

        // ---- S = Q K^T (fp16 k16), 4 k-steps over d=64 ----
        float sacc[2][8][4];
        #pragma unroll
        for (int mi = 0; mi < 2; mi++)
            #pragma unroll
            for (int ni = 0; ni < 8; ni++)
                #pragma unroll
                for (int r = 0; r < 4; r++) sacc[mi][ni][r] = 0.0f;

        #pragma unroll
        for (int kk = 0; kk < 4; kk++) {
            uint32_t bf[8][2];
            #pragma unroll
            for (int ni = 0; ni < 8; ni++) {
                bf[ni][0] = Kw[(ni * 8 + g) * KW_P + kk * 8 + tig];
                bf[ni][1] = Kw[(ni * 8 + g) * KW_P + kk * 8 + 4 + tig];
            }
            #pragma unroll
            for (int mi = 0; mi < 2; mi++)
                #pragma unroll
                for (int ni = 0; ni < 8; ni++)
                    mma_fp16(sacc[mi][ni], Qf[mi][kk], bf[ni]);
        }

        // ---- softmax: half2 pack -> HFMA2(scale,bias) -> ex2.f16x2 ----
        uint32_t pp[2][8][2];
        #pragma unroll
        for (int mi = 0; mi < 2; mi++)
            #pragma unroll
            for (int ni = 0; ni < 8; ni++) {
                uint32_t b2 = mw[ni * 4 + tig];
                uint32_t a01 = pack_half2(sacc[mi][ni][0], sacc[mi][ni][1]);
                uint32_t a23 = pack_half2(sacc[mi][ni][2], sacc[mi][ni][3]);
                pp[mi][ni][0] = h2_fma_ex2(a01, sc2x2, b2);
                pp[mi][ni][1] = h2_fma_ex2(a23, sc2x2, b2);
            }

        // ---- O += P V and row sums += P 1 (fp16 k16) ----
        #pragma unroll
        for (int kb = 0; kb < 4; kb++) {
            uint32_t bf[8][2];
            #pragma unroll
            for (int ni = 0; ni < 8; ni++) {
                bf[ni][0] = Vw[(ni * 8 + g) * VW_P + kb * 8 + tig];
                bf[ni][1] = Vw[(ni * 8 + g) * VW_P + kb * 8 + 4 + tig];
            }
            #pragma unroll
            for (int mi = 0; mi < 2; mi++) {
                uint32_t a[4] = { pp[mi][2 * kb][0],     pp[mi][2 * kb][1],
                                  pp[mi][2 * kb + 1][0], pp[mi][2 * kb + 1][1] };
                #pragma unroll
                for (int ni = 0; ni < 8; ni++)
                    mma_fp16(accO[mi][ni], a, bf[ni]);
                mma_fp16(accS[mi], a, onesb);   // row sums on tensor pipe
            }
        }

        __syncthreads();
        if (kt + 3 < FA_NCHUNK) issue(kt + 3);
    }

    // ---- epilogue: rowl from accS (cols duplicated), write packed o ----
    uint32_t* ohp = g_oh + (size_t)b * (CDIM / 2) * TDIM
                  + (size_t)(h * (HDIM / 2)) * TDIM + tt * FA_TBLK + tw;
    #pragma unroll
    for (int mi = 0; mi < 2; mi++) {
        float il0 = 1.0f / accS[mi][0];   // row g
        float il1 = 1.0f / accS[mi][2];   // row g+8
        #pragma unroll
        for (int ni = 0; ni < 8; ni++) {
            int dw = ni * 4 + tig;
            uint32_t* op = ohp + (size_t)dw * TDIM + mi * 16 + g;
            op[0] = pack_half2(accO[mi][ni][0] * il0, accO[mi][ni][1] * il0);
            op[8] = pack_half2(accO[mi][ni][2] * il1, accO[mi][ni][3] * il1);
        }
    }
}

// ---------------------------------------------------------------------------
// kernel_launch (single stream, graph-safe)
// ---------------------------------------------------------------------------
extern "C" void kernel_launch(void* const* d_in, const int* in_sizes, int n_in,
                              void* d_out, int out_size)
{
    const float* x    = (const float*)d_in[0];
    const int*   mask = (const int*)  d_in[1];
    const float* Wqkv = (const float*)d_in[2];
    const float* bqkv = (const float*)d_in[3];
    const float* Wout = (const float*)d_in[4];
    const float* bout = (const float*)d_in[5];
    float*       out  = (float*)d_out;

    __half *qt_p, *kt_p, *vh_p, *wqh_p, *woh_p;
    uint32_t *oh_p, *xh_p;
    cudaGetSymbolAddress((void**)&qt_p,  g_qt);
    cudaGetSymbolAddress((void**)&kt_p,  g_kt);
    cudaGetSymbolAddress((void**)&vh_p,  g_vh);
    cudaGetSymbolAddress((void**)&oh_p,  g_oh);
    cudaGetSymbolAddress((void**)&xh_p,  g_xh);
    cudaGetSymbolAddress((void**)&wqh_p, g_wqh);
    cudaGetSymbolAddress((void**)&woh_p, g_woh);

    cudaFuncSetAttribute(gemm_fp16_cp<0>,
                         cudaFuncAttributeMaxDynamicSharedMemorySize, GEMM_SMEM_BYTES);
    cudaFuncSetAttribute(gemm_fp16_cp<1>,
                         cudaFuncAttributeMaxDynamicSharedMemorySize, GEMM_SMEM_BYTES);
    cudaFuncSetAttribute(flash_attn_v12,
                         cudaFuncAttributeMaxDynamicSharedMemorySize, FA_SMEM_BYTES);

    // 0) pack inputs to fp16
    {
        const int nq = QKVROWS * CDIM;
        const int nw = CDIM * CDIM;
        const int nxw4 = BATCH * (CDIM / 2) * (TDIM / 4);
        pack_w_kernel<<<nq / 1024, 256>>>(Wqkv, wqh_p, nq);
        pack_w_kernel<<<nw / 1024, 256>>>(Wout, woh_p, nw);
        pack_x_kernel<<<nxw4 / 256, 256>>>(x, xh_p);
    }

    // 1) qkv = Wqkv @ x + bqkv  (Q -> qT, K -> kT, V -> vh, all fp16)
    {
        dim3 grid(TDIM / 128, QKVROWS / 128, BATCH);
        gemm_fp16_cp<1><<<grid, 128, GEMM_SMEM_BYTES>>>(
            wqh_p, xh_p, bqkv, nullptr, qt_p, kt_p, vh_p, QKVROWS, TDIM, CDIM);
    }
    // 2) fused flash attention
    {
        dim3 grid(TDIM / FA_TBLK, NHEAD, BATCH);
        flash_attn_v12<<<grid, 256, FA_SMEM_BYTES>>>(mask);
    }
    // 3) out = Wout @ o + bout  (fp16 GEMM, f32 out)
    {
        dim3 grid(TDIM / 128, CDIM / 128, BATCH);
        gemm_fp16_cp<0><<<grid, 128, GEMM_SMEM_BYTES>>>(
            woh_p, oh_p, bout, out, nullptr, nullptr, nullptr, CDIM, TDIM, CDIM);
    }
}